// round 1
// baseline (speedup 1.0000x reference)
#include <cuda_runtime.h>
#include <math.h>
#include <stdint.h>

// ---------------- problem constants (l = 2, 76x76 head) ----------------
#define IN_H   76
#define IN_W   76
#define PLANE  (IN_H * IN_W)        // 5776
#define BS     32
#define NT     20                   // targets per image
#define NA     3                    // anchors at this level
#define NC     80
#define CELLS  (NA * PLANE)         // 17328 per batch item
#define EPSF   1e-7f

// scaled anchors = ANCHORS / stride(=8); mask for l=2 is anchors [0,1,2]
__device__ __constant__ float c_aw9[9] = {1.5f, 2.375f, 5.f, 4.5f, 9.5f, 9.f, 17.75f, 24.f, 57.375f};
__device__ __constant__ float c_ah9[9] = {2.f, 4.5f, 3.5f, 9.375f, 6.875f, 18.25f, 13.75f, 30.375f, 50.125f};
__device__ __constant__ float c_awl[3] = {1.5f, 2.375f, 5.f};
__device__ __constant__ float c_ahl[3] = {2.f, 4.5f, 3.5f};

// loss ratios
#define BOX_RATIO 0.05
#define CLS_RATIO 1.0
#define BALANCE_L 4.0
#define OBJ_RATIO (5.0 * 608.0 * 608.0 / (416.0 * 416.0))

// ---------------- device scratch (static, no allocation) ----------------
struct Matched { int b, a, gi, gj, cls; float gx, gy, gw, gh; };

__device__ double g_conf_num;   // sum bce(conf, tgt)*mask
__device__ double g_mask_sum;   // sum conf_mask
__device__ double g_loc_sum;    // sum (1 - ciou) over obj cells
__device__ double g_cls_sum;    // sum bce over obj cells x 80 classes
__device__ int    g_mcount;     // number of distinct matched cells (= sum obj)
__device__ Matched g_matched[BS * NT];

__device__ __forceinline__ float sigf(float x) { return 1.f / (1.f + expf(-x)); }
__device__ __forceinline__ float clampp(float p) { return fminf(fmaxf(p, EPSF), 1.f - EPSF); }

// ---------------- kernel 0: reset accumulators ----------------
__global__ void k_zero() {
    g_conf_num = 0.0; g_mask_sum = 0.0; g_loc_sum = 0.0; g_cls_sum = 0.0; g_mcount = 0;
}

// ---------------- kernel 1: target->anchor matching + last-wins dedupe ----------------
__global__ void k_match(const float* __restrict__ targets) {
    int b = threadIdx.x;
    if (b >= BS) return;

    int   flat[NT];
    float gx[NT], gy[NT], gw[NT], gh[NT];
    int   cls[NT];

    for (int t = 0; t < NT; t++) {
        const float* tp = targets + (b * NT + t) * 5;
        float x = tp[0] * (float)IN_W;
        float y = tp[1] * (float)IN_H;
        float w = tp[2] * (float)IN_W;
        float h = tp[3] * (float)IN_H;
        // zero-centered wh IoU against all 9 anchors, argmax (first max wins)
        float best = -1.f; int bn = 0;
        for (int a = 0; a < 9; a++) {
            float inter = fminf(w, c_aw9[a]) * fminf(h, c_ah9[a]);
            float uni   = w * h + c_aw9[a] * c_ah9[a] - inter;
            float r = inter / uni;
            if (r > best) { best = r; bn = a; }
        }
        if (bn < NA) {  // ANCHORS_MASK[2] = [0,1,2]
            int gi = (int)floorf(x); gi = min(max(gi, 0), IN_W - 1);
            int gj = (int)floorf(y); gj = min(max(gj, 0), IN_H - 1);
            flat[t] = (bn * IN_H + gj) * IN_W + gi;
            gx[t] = x; gy[t] = y; gw[t] = w; gh[t] = h; cls[t] = (int)tp[4];
        } else {
            flat[t] = -1;
        }
    }
    // last-wins: entry t is final iff no later valid t' hits the same cell
    for (int t = 0; t < NT; t++) {
        if (flat[t] < 0) continue;
        bool fin = true;
        for (int t2 = t + 1; t2 < NT; t2++)
            if (flat[t2] == flat[t]) { fin = false; break; }
        if (!fin) continue;
        int idx = atomicAdd(&g_mcount, 1);
        Matched m;
        m.b = b;
        m.a = flat[t] / PLANE;
        int rem = flat[t] % PLANE;
        m.gj = rem / IN_W; m.gi = rem % IN_W;
        m.gx = gx[t]; m.gy = gy[t]; m.gw = gw[t]; m.gh = gh[t]; m.cls = cls[t];
        g_matched[idx] = m;
    }
}

// ---------------- kernel 2: dense pass — conf loss assuming obj=0 everywhere ----------------
__global__ void __launch_bounds__(256) k_main(const float* __restrict__ input,
                                              const float* __restrict__ targets) {
    const int b = blockIdx.y;
    const int m = blockIdx.x * blockDim.x + threadIdx.x;

    __shared__ float sminx[NT], smaxx[NT], sminy[NT], smaxy[NT], sarea[NT];
    if (threadIdx.x < NT) {
        const float* tp = targets + (b * NT + threadIdx.x) * 5;
        float gx = tp[0] * (float)IN_W, gy = tp[1] * (float)IN_H;
        float gw = tp[2] * (float)IN_W, gh = tp[3] * (float)IN_H;
        sminx[threadIdx.x] = gx - gw * 0.5f; smaxx[threadIdx.x] = gx + gw * 0.5f;
        sminy[threadIdx.x] = gy - gh * 0.5f; smaxy[threadIdx.x] = gy + gh * 0.5f;
        sarea[threadIdx.x] = gw * gh;
    }
    __syncthreads();

    float cnum = 0.f, cmask = 0.f;
    if (m < CELLS) {
        int a   = m / PLANE;
        int rem = m - a * PLANE;
        int i   = rem / IN_W;
        int j   = rem - i * IN_W;

        const float* base = input + ((size_t)b * 255 + (size_t)a * 85) * PLANE + rem;
        float tx = base[0];
        float ty = base[PLANE];
        float tw = base[2 * PLANE];
        float th = base[3 * PLANE];
        float tc = base[4 * PLANE];

        float px = (float)j + sigf(tx);
        float py = (float)i + sigf(ty);
        float pw = expf(tw) * c_awl[a];
        float ph = expf(th) * c_ahl[a];

        float pminx = px - pw * 0.5f, pmaxx = px + pw * 0.5f;
        float pminy = py - ph * 0.5f, pmaxy = py + ph * 0.5f;
        float pa = pw * ph;

        float best = -1e30f;
        #pragma unroll
        for (int t = 0; t < NT; t++) {
            float iw = fmaxf(fminf(smaxx[t], pmaxx) - fmaxf(sminx[t], pminx), 0.f);
            float ih = fmaxf(fminf(smaxy[t], pmaxy) - fmaxf(sminy[t], pminy), 0.f);
            float inter = iw * ih;
            float iou = inter / (sarea[t] + pa - inter);
            best = fmaxf(best, iou);
        }
        float noobj = (best > 0.5f) ? 0.f : 1.f;
        float conf = clampp(sigf(tc));
        cnum  = -logf(1.f - conf) * noobj;   // bce(conf, 0) * noobj
        cmask = noobj;
    }

    // warp + block reduction, one double atomic pair per block
    #pragma unroll
    for (int o = 16; o > 0; o >>= 1) {
        cnum  += __shfl_down_sync(0xffffffffu, cnum,  o);
        cmask += __shfl_down_sync(0xffffffffu, cmask, o);
    }
    __shared__ float rn[8], rm[8];
    int wid = threadIdx.x >> 5, lane = threadIdx.x & 31;
    if (lane == 0) { rn[wid] = cnum; rm[wid] = cmask; }
    __syncthreads();
    if (wid == 0) {
        float n = (lane < 8) ? rn[lane] : 0.f;
        float k = (lane < 8) ? rm[lane] : 0.f;
        #pragma unroll
        for (int o = 4; o > 0; o >>= 1) {
            n += __shfl_down_sync(0xffffffffu, n, o);
            k += __shfl_down_sync(0xffffffffu, k, o);
        }
        if (lane == 0) {
            atomicAdd(&g_conf_num, (double)n);
            atomicAdd(&g_mask_sum, (double)k);
        }
    }
}

// ---------------- kernel 3: matched-cell loc/cls + conf correction ----------------
__global__ void k_corr(const float* __restrict__ input,
                       const float* __restrict__ targets) {
    int idx = blockIdx.x * blockDim.x + threadIdx.x;
    if (idx >= g_mcount) return;
    Matched M = g_matched[idx];

    const float* base = input + ((size_t)M.b * 255 + (size_t)M.a * 85) * PLANE
                              + (size_t)M.gj * IN_W + M.gi;
    float tx = base[0];
    float ty = base[PLANE];
    float tw = base[2 * PLANE];
    float th = base[3 * PLANE];
    float tc = base[4 * PLANE];

    float px = (float)M.gi + sigf(tx);
    float py = (float)M.gj + sigf(ty);
    float pw = expf(tw) * c_awl[M.a];
    float ph = expf(th) * c_ahl[M.a];

    // ---- CIoU exactly per reference ----
    float b1minx = px - pw * 0.5f, b1maxx = px + pw * 0.5f;
    float b1miny = py - ph * 0.5f, b1maxy = py + ph * 0.5f;
    float b2minx = M.gx - M.gw * 0.5f, b2maxx = M.gx + M.gw * 0.5f;
    float b2miny = M.gy - M.gh * 0.5f, b2maxy = M.gy + M.gh * 0.5f;
    float iw = fmaxf(fminf(b1maxx, b2maxx) - fmaxf(b1minx, b2minx), 0.f);
    float ih = fmaxf(fminf(b1maxy, b2maxy) - fmaxf(b1miny, b2miny), 0.f);
    float inter = iw * ih;
    float a1 = pw * ph, a2 = M.gw * M.gh;
    float iou = inter / fmaxf(a1 + a2 - inter, 1e-6f);
    float cdx = px - M.gx, cdy = py - M.gy;
    float center_d = cdx * cdx + cdy * cdy;
    float ew = fmaxf(fmaxf(b1maxx, b2maxx) - fminf(b1minx, b2minx), 0.f);
    float eh = fmaxf(fmaxf(b1maxy, b2maxy) - fminf(b1miny, b2miny), 0.f);
    float encl = ew * ew + eh * eh;
    float ciou = iou - center_d / fmaxf(encl, 1e-6f);
    const float FOUR_OVER_PI2 = 4.f / (float)(M_PI * M_PI);
    float dat = atanf(pw / fmaxf(ph, 1e-6f)) - atanf(M.gw / fmaxf(M.gh, 1e-6f));
    float v = FOUR_OVER_PI2 * dat * dat;
    float alpha = v / fmaxf(1.f - iou + v, 1e-6f);
    ciou = ciou - alpha * v;

    // ---- class BCE (80 classes, one-hot target) ----
    float clssum = 0.f;
    #pragma unroll 8
    for (int c = 0; c < NC; c++) {
        float p = clampp(sigf(base[(size_t)(5 + c) * PLANE]));
        clssum += (c == M.cls) ? -logf(p) : -logf(1.f - p);
    }

    // ---- conf correction: replace main-pass (obj=0) contribution ----
    float pa = pw * ph;
    float best = -1e30f;
    for (int t = 0; t < NT; t++) {
        const float* tp = targets + (M.b * NT + t) * 5;
        float gx = tp[0] * (float)IN_W, gy = tp[1] * (float)IN_H;
        float gw = tp[2] * (float)IN_W, gh = tp[3] * (float)IN_H;
        float gminx = gx - gw * 0.5f, gmaxx = gx + gw * 0.5f;
        float gminy = gy - gh * 0.5f, gmaxy = gy + gh * 0.5f;
        float iw2 = fmaxf(fminf(gmaxx, b1maxx) - fmaxf(gminx, b1minx), 0.f);
        float ih2 = fmaxf(fminf(gmaxy, b1maxy) - fmaxf(gminy, b1miny), 0.f);
        float in2 = iw2 * ih2;
        best = fmaxf(best, in2 / (gw * gh + pa - in2));
    }
    float noobj0 = (best > 0.5f) ? 0.f : 1.f;
    float conf = clampp(sigf(tc));
    float add = -logf(conf);                 // bce(conf, 1) with mask 1
    float sub = -logf(1.f - conf) * noobj0;  // what k_main already added

    atomicAdd(&g_conf_num, (double)(add - sub));
    atomicAdd(&g_mask_sum, (double)(1.f - noobj0));
    atomicAdd(&g_loc_sum,  (double)(1.f - ciou));
    atomicAdd(&g_cls_sum,  (double)clssum);
}

// ---------------- kernel 4: assemble scalar loss ----------------
__global__ void k_final(float* __restrict__ out) {
    double nobj = (g_mcount > 0) ? (double)g_mcount : 1.0;
    double loss = g_loc_sum / nobj * BOX_RATIO
                + g_cls_sum / (nobj * (double)NC) * CLS_RATIO
                + g_conf_num / fmax(g_mask_sum, 1.0) * BALANCE_L * OBJ_RATIO;
    out[0] = (float)loss;
}

// ---------------- launcher ----------------
extern "C" void kernel_launch(void* const* d_in, const int* in_sizes, int n_in,
                              void* d_out, int out_size) {
    const float* input   = (const float*)d_in[0];
    const float* targets = (const float*)d_in[1];
    float* out = (float*)d_out;
    (void)in_sizes; (void)n_in; (void)out_size;

    k_zero<<<1, 1>>>();
    k_match<<<1, 32>>>(targets);
    dim3 grid((CELLS + 255) / 256, BS);
    k_main<<<grid, 256>>>(input, targets);
    k_corr<<<5, 128>>>(input, targets);
    k_final<<<1, 1>>>(out);
}

// round 2
// speedup vs baseline: 1.2647x; 1.2647x over previous
#include <cuda_runtime.h>
#include <math.h>
#include <stdint.h>

// ---------------- problem constants (l = 2, 76x76 head) ----------------
#define IN_H   76
#define IN_W   76
#define PLANE  (IN_H * IN_W)        // 5776
#define BS     32
#define NT     20                   // targets per image
#define NA     3                    // anchors at this level
#define NC     80
#define CELLS  (NA * PLANE)         // 17328 per batch item
#define EPSF   1e-7f

// scaled anchors = ANCHORS / stride(=8); mask for l=2 is anchors [0,1,2]
__device__ __constant__ float c_aw9[9] = {1.5f, 2.375f, 5.f, 4.5f, 9.5f, 9.f, 17.75f, 24.f, 57.375f};
__device__ __constant__ float c_ah9[9] = {2.f, 4.5f, 3.5f, 9.375f, 6.875f, 18.25f, 13.75f, 30.375f, 50.125f};
__device__ __constant__ float c_awl[3] = {1.5f, 2.375f, 5.f};
__device__ __constant__ float c_ahl[3] = {2.f, 4.5f, 3.5f};

// loss ratios
#define BOX_RATIO 0.05
#define CLS_RATIO 1.0
#define BALANCE_L 4.0
#define OBJ_RATIO (5.0 * 608.0 * 608.0 / (416.0 * 416.0))

// ---------------- device scratch (static, no allocation) ----------------
struct Matched { int b, a, gi, gj, cls; float gx, gy, gw, gh; };

__device__ double g_conf_num;   // sum bce(conf, tgt)*mask
__device__ double g_mask_sum;   // sum conf_mask
__device__ double g_loc_sum;    // sum (1 - ciou) over obj cells
__device__ double g_cls_sum;    // sum bce over obj cells x 80 classes
__device__ int    g_mcount;     // number of distinct matched cells (= sum obj)
__device__ Matched g_matched[BS * NT];

__device__ __forceinline__ float sigf(float x) { return 1.f / (1.f + expf(-x)); }
__device__ __forceinline__ float clampp(float p) { return fminf(fmaxf(p, EPSF), 1.f - EPSF); }

// ---------------- kernel 1: zero accumulators + target->anchor matching ----------------
__global__ void k_match(const float* __restrict__ targets) {
    int b = threadIdx.x;
    if (b == 0) {
        g_conf_num = 0.0; g_mask_sum = 0.0; g_loc_sum = 0.0; g_cls_sum = 0.0; g_mcount = 0;
    }
    __syncthreads();
    if (b >= BS) return;

    int   flat[NT];
    float gx[NT], gy[NT], gw[NT], gh[NT];
    int   cls[NT];

    for (int t = 0; t < NT; t++) {
        const float* tp = targets + (b * NT + t) * 5;
        float x = tp[0] * (float)IN_W;
        float y = tp[1] * (float)IN_H;
        float w = tp[2] * (float)IN_W;
        float h = tp[3] * (float)IN_H;
        // zero-centered wh IoU against all 9 anchors, argmax (first max wins)
        float best = -1.f; int bn = 0;
        for (int a = 0; a < 9; a++) {
            float inter = fminf(w, c_aw9[a]) * fminf(h, c_ah9[a]);
            float uni   = w * h + c_aw9[a] * c_ah9[a] - inter;
            float r = inter / uni;
            if (r > best) { best = r; bn = a; }
        }
        if (bn < NA) {  // ANCHORS_MASK[2] = [0,1,2]
            int gi = (int)floorf(x); gi = min(max(gi, 0), IN_W - 1);
            int gj = (int)floorf(y); gj = min(max(gj, 0), IN_H - 1);
            flat[t] = (bn * IN_H + gj) * IN_W + gi;
            gx[t] = x; gy[t] = y; gw[t] = w; gh[t] = h; cls[t] = (int)tp[4];
        } else {
            flat[t] = -1;
        }
    }
    // last-wins: entry t is final iff no later valid t' hits the same cell
    for (int t = 0; t < NT; t++) {
        if (flat[t] < 0) continue;
        bool fin = true;
        for (int t2 = t + 1; t2 < NT; t2++)
            if (flat[t2] == flat[t]) { fin = false; break; }
        if (!fin) continue;
        int idx = atomicAdd(&g_mcount, 1);
        Matched m;
        m.b = b;
        m.a = flat[t] / PLANE;
        int rem = flat[t] % PLANE;
        m.gj = rem / IN_W; m.gi = rem % IN_W;
        m.gx = gx[t]; m.gy = gy[t]; m.gw = gw[t]; m.gh = gh[t]; m.cls = cls[t];
        g_matched[idx] = m;
    }
}

// ---------------- kernel 2: dense pass — conf loss assuming obj=0 everywhere ----------------
#define CPB 2048                       // cells per block (256 thr x 8)
#define NXB ((CELLS + CPB - 1) / CPB)  // 9 x-blocks
__global__ void __launch_bounds__(256) k_main(const float* __restrict__ input,
                                              const float* __restrict__ targets) {
    const int b = blockIdx.y;

    __shared__ float sminx[NT], smaxx[NT], sminy[NT], smaxy[NT], sarea[NT];
    if (threadIdx.x < NT) {
        const float* tp = targets + (b * NT + threadIdx.x) * 5;
        float gx = tp[0] * (float)IN_W, gy = tp[1] * (float)IN_H;
        float gw = tp[2] * (float)IN_W, gh = tp[3] * (float)IN_H;
        sminx[threadIdx.x] = gx - gw * 0.5f; smaxx[threadIdx.x] = gx + gw * 0.5f;
        sminy[threadIdx.x] = gy - gh * 0.5f; smaxy[threadIdx.x] = gy + gh * 0.5f;
        sarea[threadIdx.x] = gw * gh;
    }
    __syncthreads();

    float cnum = 0.f, cmask = 0.f;
    const float* binp = input + (size_t)b * 255 * PLANE;

    #pragma unroll
    for (int chunk = 0; chunk < 8; chunk++) {
        int m = blockIdx.x * CPB + chunk * 256 + threadIdx.x;
        if (m >= CELLS) break;
        int a   = m / PLANE;
        int rem = m - a * PLANE;
        int i   = rem / IN_W;
        int j   = rem - i * IN_W;

        const float* base = binp + (size_t)a * 85 * PLANE + rem;
        float tx = base[0];
        float ty = base[PLANE];
        float tw = base[2 * PLANE];
        float th = base[3 * PLANE];
        float tc = base[4 * PLANE];

        float px = (float)j + sigf(tx);
        float py = (float)i + sigf(ty);
        float pw = expf(tw) * c_awl[a];
        float ph = expf(th) * c_ahl[a];

        float pminx = px - pw * 0.5f, pmaxx = px + pw * 0.5f;
        float pminy = py - ph * 0.5f, pmaxy = py + ph * 0.5f;
        float pa = pw * ph;

        float best = -1e30f;
        #pragma unroll
        for (int t = 0; t < NT; t++) {
            float iw = fmaxf(fminf(smaxx[t], pmaxx) - fmaxf(sminx[t], pminx), 0.f);
            float ih = fmaxf(fminf(smaxy[t], pmaxy) - fmaxf(sminy[t], pminy), 0.f);
            float inter = iw * ih;
            float iou = inter / (sarea[t] + pa - inter);
            best = fmaxf(best, iou);
        }
        float noobj = (best > 0.5f) ? 0.f : 1.f;
        float conf = clampp(sigf(tc));
        cnum  += -logf(1.f - conf) * noobj;   // bce(conf, 0) * noobj
        cmask += noobj;
    }

    // warp + block reduction, one double atomic pair per block
    #pragma unroll
    for (int o = 16; o > 0; o >>= 1) {
        cnum  += __shfl_down_sync(0xffffffffu, cnum,  o);
        cmask += __shfl_down_sync(0xffffffffu, cmask, o);
    }
    __shared__ float rn[8], rm[8];
    int wid = threadIdx.x >> 5, lane = threadIdx.x & 31;
    if (lane == 0) { rn[wid] = cnum; rm[wid] = cmask; }
    __syncthreads();
    if (wid == 0) {
        float n = (lane < 8) ? rn[lane] : 0.f;
        float k = (lane < 8) ? rm[lane] : 0.f;
        #pragma unroll
        for (int o = 4; o > 0; o >>= 1) {
            n += __shfl_down_sync(0xffffffffu, n, o);
            k += __shfl_down_sync(0xffffffffu, k, o);
        }
        if (lane == 0) {
            atomicAdd(&g_conf_num, (double)n);
            atomicAdd(&g_mask_sum, (double)k);
        }
    }
}

// ---------------- kernel 3: matched-cell loc/cls + conf correction (1 warp / cell) ----------------
__global__ void __launch_bounds__(256) k_corr(const float* __restrict__ input,
                                              const float* __restrict__ targets) {
    const int lane = threadIdx.x & 31;
    const int widx = (blockIdx.x * blockDim.x + threadIdx.x) >> 5;  // global warp id

    __shared__ double s_conf, s_mask, s_loc, s_cls;
    if (threadIdx.x == 0) { s_conf = 0.0; s_mask = 0.0; s_loc = 0.0; s_cls = 0.0; }
    __syncthreads();

    if (widx < g_mcount) {
        Matched M = g_matched[widx];
        const float* base = input + ((size_t)M.b * 255 + (size_t)M.a * 85) * PLANE
                                  + (size_t)M.gj * IN_W + M.gi;

        // lanes 0..4 fetch the 5 box channels; broadcast via shuffle
        float v5 = (lane < 5) ? base[(size_t)lane * PLANE] : 0.f;
        float tx = __shfl_sync(0xffffffffu, v5, 0);
        float ty = __shfl_sync(0xffffffffu, v5, 1);
        float tw = __shfl_sync(0xffffffffu, v5, 2);
        float th = __shfl_sync(0xffffffffu, v5, 3);
        float tc = __shfl_sync(0xffffffffu, v5, 4);

        // class BCE: 80 channels split across 32 lanes (MLP = warp-wide)
        float clssum = 0.f;
        #pragma unroll
        for (int c = lane; c < NC; c += 32) {
            float p = clampp(sigf(base[(size_t)(5 + c) * PLANE]));
            clssum += (c == M.cls) ? -logf(p) : -logf(1.f - p);
        }

        float px = (float)M.gi + sigf(tx);
        float py = (float)M.gj + sigf(ty);
        float pw = expf(tw) * c_awl[M.a];
        float ph = expf(th) * c_ahl[M.a];
        float b1minx = px - pw * 0.5f, b1maxx = px + pw * 0.5f;
        float b1miny = py - ph * 0.5f, b1maxy = py + ph * 0.5f;
        float pa = pw * ph;

        // ignore-IoU vs 20 gt boxes: lane t handles target t
        float iou_t = -1e30f;
        if (lane < NT) {
            const float* tp = targets + (M.b * NT + lane) * 5;
            float gx = tp[0] * (float)IN_W, gy = tp[1] * (float)IN_H;
            float gw = tp[2] * (float)IN_W, gh = tp[3] * (float)IN_H;
            float gminx = gx - gw * 0.5f, gmaxx = gx + gw * 0.5f;
            float gminy = gy - gh * 0.5f, gmaxy = gy + gh * 0.5f;
            float iw2 = fmaxf(fminf(gmaxx, b1maxx) - fmaxf(gminx, b1minx), 0.f);
            float ih2 = fmaxf(fminf(gmaxy, b1maxy) - fmaxf(gminy, b1miny), 0.f);
            float in2 = iw2 * ih2;
            iou_t = in2 / (gw * gh + pa - in2);
        }
        // warp reductions: sum(clssum), max(iou_t)
        #pragma unroll
        for (int o = 16; o > 0; o >>= 1) {
            clssum += __shfl_down_sync(0xffffffffu, clssum, o);
            iou_t = fmaxf(iou_t, __shfl_down_sync(0xffffffffu, iou_t, o));
        }

        if (lane == 0) {
            // ---- CIoU exactly per reference ----
            float b2minx = M.gx - M.gw * 0.5f, b2maxx = M.gx + M.gw * 0.5f;
            float b2miny = M.gy - M.gh * 0.5f, b2maxy = M.gy + M.gh * 0.5f;
            float iw = fmaxf(fminf(b1maxx, b2maxx) - fmaxf(b1minx, b2minx), 0.f);
            float ih = fmaxf(fminf(b1maxy, b2maxy) - fmaxf(b1miny, b2miny), 0.f);
            float inter = iw * ih;
            float a1 = pa, a2 = M.gw * M.gh;
            float iou = inter / fmaxf(a1 + a2 - inter, 1e-6f);
            float cdx = px - M.gx, cdy = py - M.gy;
            float center_d = cdx * cdx + cdy * cdy;
            float ew = fmaxf(fmaxf(b1maxx, b2maxx) - fminf(b1minx, b2minx), 0.f);
            float eh = fmaxf(fmaxf(b1maxy, b2maxy) - fminf(b1miny, b2miny), 0.f);
            float encl = ew * ew + eh * eh;
            float ciou = iou - center_d / fmaxf(encl, 1e-6f);
            const float FOUR_OVER_PI2 = 4.f / (float)(M_PI * M_PI);
            float dat = atanf(pw / fmaxf(ph, 1e-6f)) - atanf(M.gw / fmaxf(M.gh, 1e-6f));
            float v = FOUR_OVER_PI2 * dat * dat;
            float alpha = v / fmaxf(1.f - iou + v, 1e-6f);
            ciou = ciou - alpha * v;

            // ---- conf correction: replace main-pass (obj=0) contribution ----
            float noobj0 = (iou_t > 0.5f) ? 0.f : 1.f;
            float conf = clampp(sigf(tc));
            float add = -logf(conf);                 // bce(conf, 1) with mask 1
            float sub = -logf(1.f - conf) * noobj0;  // what k_main already added

            atomicAdd(&s_conf, (double)(add - sub));
            atomicAdd(&s_mask, (double)(1.f - noobj0));
            atomicAdd(&s_loc,  (double)(1.f - ciou));
            atomicAdd(&s_cls,  (double)clssum);
        }
    }

    __syncthreads();
    if (threadIdx.x == 0) {
        atomicAdd(&g_conf_num, s_conf);
        atomicAdd(&g_mask_sum, s_mask);
        atomicAdd(&g_loc_sum,  s_loc);
        atomicAdd(&g_cls_sum,  s_cls);
    }
}

// ---------------- kernel 4: assemble scalar loss ----------------
__global__ void k_final(float* __restrict__ out) {
    double nobj = (g_mcount > 0) ? (double)g_mcount : 1.0;
    double loss = g_loc_sum / nobj * BOX_RATIO
                + g_cls_sum / (nobj * (double)NC) * CLS_RATIO
                + g_conf_num / fmax(g_mask_sum, 1.0) * BALANCE_L * OBJ_RATIO;
    out[0] = (float)loss;
}

// ---------------- launcher ----------------
extern "C" void kernel_launch(void* const* d_in, const int* in_sizes, int n_in,
                              void* d_out, int out_size) {
    const float* input   = (const float*)d_in[0];
    const float* targets = (const float*)d_in[1];
    float* out = (float*)d_out;
    (void)in_sizes; (void)n_in; (void)out_size;

    k_match<<<1, 32>>>(targets);
    dim3 grid(NXB, BS);
    k_main<<<grid, 256>>>(input, targets);
    // max BS*NT = 640 matched cells, 1 warp each -> 640 warps = 80 blocks x 8 warps
    k_corr<<<80, 256>>>(input, targets);
    k_final<<<1, 1>>>(out);
}

// round 3
// speedup vs baseline: 1.8890x; 1.4937x over previous
#include <cuda_runtime.h>
#include <math.h>
#include <stdint.h>

// ---------------- problem constants (l = 2, 76x76 head) ----------------
#define IN_H   76
#define IN_W   76
#define PLANE  (IN_H * IN_W)        // 5776
#define BS     32
#define NT     20                   // targets per image
#define NA     3
#define NC     80
#define CELLS  (NA * PLANE)         // 17328 per batch item
#define EPSF   1e-7f

__device__ __constant__ float c_aw9[9] = {1.5f, 2.375f, 5.f, 4.5f, 9.5f, 9.f, 17.75f, 24.f, 57.375f};
__device__ __constant__ float c_ah9[9] = {2.f, 4.5f, 3.5f, 9.375f, 6.875f, 18.25f, 13.75f, 30.375f, 50.125f};
__device__ __constant__ float c_awl[3] = {1.5f, 2.375f, 5.f};
__device__ __constant__ float c_ahl[3] = {2.f, 4.5f, 3.5f};

#define BOX_RATIO 0.05
#define CLS_RATIO 1.0
#define BALANCE_L 4.0
#define OBJ_RATIO (5.0 * 608.0 * 608.0 / (416.0 * 416.0))

// ---------------- device scratch ----------------
struct Matched { int b, a, gi, gj, cls; float gx, gy, gw, gh; };

__device__ double g_conf_num;
__device__ double g_mask_sum;
__device__ double g_loc_sum;
__device__ double g_cls_sum;
__device__ int    g_mcount;
__device__ int    g_done;
__device__ Matched g_matched[BS * NT];

__device__ __forceinline__ float sigfast(float x) { return __fdividef(1.f, 1.f + __expf(-x)); }
// softplus(x) = -log(1 - sigmoid(x)) = bce(sigmoid(x), 0); also bce(sigmoid(x),1) = softplus(-x)
__device__ __forceinline__ float splus(float x) { return __logf(1.f + __expf(x)); }

// ---------------- kernel 1: zero accumulators + target->anchor matching ----------------
__global__ void k_match(const float* __restrict__ targets) {
    int b = threadIdx.x;
    if (b == 0) {
        g_conf_num = 0.0; g_mask_sum = 0.0; g_loc_sum = 0.0; g_cls_sum = 0.0;
        g_mcount = 0; g_done = 0;
    }
    __syncthreads();
    if (b >= BS) return;

    int   flat[NT];
    float gx[NT], gy[NT], gw[NT], gh[NT];
    int   cls[NT];

    for (int t = 0; t < NT; t++) {
        const float* tp = targets + (b * NT + t) * 5;
        float x = tp[0] * (float)IN_W;
        float y = tp[1] * (float)IN_H;
        float w = tp[2] * (float)IN_W;
        float h = tp[3] * (float)IN_H;
        float best = -1.f; int bn = 0;
        for (int a = 0; a < 9; a++) {
            float inter = fminf(w, c_aw9[a]) * fminf(h, c_ah9[a]);
            float uni   = w * h + c_aw9[a] * c_ah9[a] - inter;
            float r = inter / uni;
            if (r > best) { best = r; bn = a; }
        }
        if (bn < NA) {
            int gi = (int)floorf(x); gi = min(max(gi, 0), IN_W - 1);
            int gj = (int)floorf(y); gj = min(max(gj, 0), IN_H - 1);
            flat[t] = (bn * IN_H + gj) * IN_W + gi;
            gx[t] = x; gy[t] = y; gw[t] = w; gh[t] = h; cls[t] = (int)tp[4];
        } else {
            flat[t] = -1;
        }
    }
    for (int t = 0; t < NT; t++) {
        if (flat[t] < 0) continue;
        bool fin = true;
        for (int t2 = t + 1; t2 < NT; t2++)
            if (flat[t2] == flat[t]) { fin = false; break; }
        if (!fin) continue;
        int idx = atomicAdd(&g_mcount, 1);
        Matched m;
        m.b = b;
        m.a = flat[t] / PLANE;
        int rem = flat[t] % PLANE;
        m.gj = rem / IN_W; m.gi = rem % IN_W;
        m.gx = gx[t]; m.gy = gy[t]; m.gw = gw[t]; m.gh = gh[t]; m.cls = cls[t];
        g_matched[idx] = m;
    }
}

// ---------------- kernel 2: dense conf pass (obj=0 everywhere) ----------------
#define CPB 512                        // cells per block (256 thr x 2)
#define NXB ((CELLS + CPB - 1) / CPB)  // 34 x-blocks
__global__ void __launch_bounds__(256) k_main(const float* __restrict__ input,
                                              const float* __restrict__ targets) {
    const int b = blockIdx.y;

    __shared__ float sminx[NT], smaxx[NT], sminy[NT], smaxy[NT], sarea[NT];
    if (threadIdx.x < NT) {
        const float* tp = targets + (b * NT + threadIdx.x) * 5;
        float gx = tp[0] * (float)IN_W, gy = tp[1] * (float)IN_H;
        float gw = tp[2] * (float)IN_W, gh = tp[3] * (float)IN_H;
        sminx[threadIdx.x] = gx - gw * 0.5f; smaxx[threadIdx.x] = gx + gw * 0.5f;
        sminy[threadIdx.x] = gy - gh * 0.5f; smaxy[threadIdx.x] = gy + gh * 0.5f;
        sarea[threadIdx.x] = gw * gh;
    }
    __syncthreads();

    float cnum = 0.f, cmask = 0.f;
    const float* binp = input + (size_t)b * 255 * PLANE;

    #pragma unroll
    for (int chunk = 0; chunk < CPB / 256; chunk++) {
        int m = blockIdx.x * CPB + chunk * 256 + threadIdx.x;
        if (m >= CELLS) break;
        int a   = m / PLANE;
        int rem = m - a * PLANE;
        int i   = rem / IN_W;
        int j   = rem - i * IN_W;

        const float* base = binp + (size_t)a * 85 * PLANE + rem;
        float tx = base[0];
        float ty = base[PLANE];
        float tw = base[2 * PLANE];
        float th = base[3 * PLANE];
        float tc = base[4 * PLANE];

        float px = (float)j + sigfast(tx);
        float py = (float)i + sigfast(ty);
        float pw = __expf(tw) * c_awl[a];
        float ph = __expf(th) * c_ahl[a];

        float pminx = px - pw * 0.5f, pmaxx = px + pw * 0.5f;
        float pminy = py - ph * 0.5f, pmaxy = py + ph * 0.5f;
        float pa = pw * ph;

        // iou > 0.5  <=>  3*inter > sarea + pa   (no division)
        bool hit = false;
        #pragma unroll
        for (int t = 0; t < NT; t++) {
            float iw = fmaxf(fminf(smaxx[t], pmaxx) - fmaxf(sminx[t], pminx), 0.f);
            float ih = fmaxf(fminf(smaxy[t], pmaxy) - fmaxf(sminy[t], pminy), 0.f);
            float inter = iw * ih;
            hit = hit || (3.f * inter > sarea[t] + pa);
        }
        float noobj = hit ? 0.f : 1.f;
        cnum  += splus(tc) * noobj;   // bce(sigmoid(tc), 0) * noobj
        cmask += noobj;
    }

    #pragma unroll
    for (int o = 16; o > 0; o >>= 1) {
        cnum  += __shfl_down_sync(0xffffffffu, cnum,  o);
        cmask += __shfl_down_sync(0xffffffffu, cmask, o);
    }
    __shared__ float rn[8], rm[8];
    int wid = threadIdx.x >> 5, lane = threadIdx.x & 31;
    if (lane == 0) { rn[wid] = cnum; rm[wid] = cmask; }
    __syncthreads();
    if (wid == 0) {
        float n = (lane < 8) ? rn[lane] : 0.f;
        float k = (lane < 8) ? rm[lane] : 0.f;
        #pragma unroll
        for (int o = 4; o > 0; o >>= 1) {
            n += __shfl_down_sync(0xffffffffu, n, o);
            k += __shfl_down_sync(0xffffffffu, k, o);
        }
        if (lane == 0) {
            atomicAdd(&g_conf_num, (double)n);
            atomicAdd(&g_mask_sum, (double)k);
        }
    }
}

// ---------------- kernel 3: matched-cell loc/cls + conf correction + final ----------------
#define CORR_BLOCKS 80
__global__ void __launch_bounds__(256) k_corr(const float* __restrict__ input,
                                              const float* __restrict__ targets,
                                              float* __restrict__ out) {
    const int lane = threadIdx.x & 31;
    const int widx = (blockIdx.x * blockDim.x + threadIdx.x) >> 5;

    __shared__ double s_conf, s_mask, s_loc, s_cls;
    if (threadIdx.x == 0) { s_conf = 0.0; s_mask = 0.0; s_loc = 0.0; s_cls = 0.0; }
    __syncthreads();

    if (widx < g_mcount) {
        Matched M = g_matched[widx];
        const float* base = input + ((size_t)M.b * 255 + (size_t)M.a * 85) * PLANE
                                  + (size_t)M.gj * IN_W + M.gi;

        float v5 = (lane < 5) ? base[(size_t)lane * PLANE] : 0.f;
        float tx = __shfl_sync(0xffffffffu, v5, 0);
        float ty = __shfl_sync(0xffffffffu, v5, 1);
        float tw = __shfl_sync(0xffffffffu, v5, 2);
        float th = __shfl_sync(0xffffffffu, v5, 3);
        float tc = __shfl_sync(0xffffffffu, v5, 4);

        // class BCE split across lanes: one-hot target
        float clssum = 0.f;
        #pragma unroll
        for (int c = lane; c < NC; c += 32) {
            float t = base[(size_t)(5 + c) * PLANE];
            clssum += (c == M.cls) ? splus(-t) : splus(t);
        }

        float px = (float)M.gi + sigfast(tx);
        float py = (float)M.gj + sigfast(ty);
        float pw = __expf(tw) * c_awl[M.a];
        float ph = __expf(th) * c_ahl[M.a];
        float b1minx = px - pw * 0.5f, b1maxx = px + pw * 0.5f;
        float b1miny = py - ph * 0.5f, b1maxy = py + ph * 0.5f;
        float pa = pw * ph;

        // ignore-IoU vs 20 gt boxes (predicate form, same as k_main)
        bool hit_t = false;
        if (lane < NT) {
            const float* tp = targets + (M.b * NT + lane) * 5;
            float gx = tp[0] * (float)IN_W, gy = tp[1] * (float)IN_H;
            float gw = tp[2] * (float)IN_W, gh = tp[3] * (float)IN_H;
            float gminx = gx - gw * 0.5f, gmaxx = gx + gw * 0.5f;
            float gminy = gy - gh * 0.5f, gmaxy = gy + gh * 0.5f;
            float iw2 = fmaxf(fminf(gmaxx, b1maxx) - fmaxf(gminx, b1minx), 0.f);
            float ih2 = fmaxf(fminf(gmaxy, b1maxy) - fmaxf(gminy, b1miny), 0.f);
            float in2 = iw2 * ih2;
            hit_t = (3.f * in2 > gw * gh + pa);
        }
        unsigned hitmask = __ballot_sync(0xffffffffu, hit_t);
        #pragma unroll
        for (int o = 16; o > 0; o >>= 1)
            clssum += __shfl_down_sync(0xffffffffu, clssum, o);

        if (lane == 0) {
            // ---- CIoU (exact reference math) ----
            float b2minx = M.gx - M.gw * 0.5f, b2maxx = M.gx + M.gw * 0.5f;
            float b2miny = M.gy - M.gh * 0.5f, b2maxy = M.gy + M.gh * 0.5f;
            float iw = fmaxf(fminf(b1maxx, b2maxx) - fmaxf(b1minx, b2minx), 0.f);
            float ih = fmaxf(fminf(b1maxy, b2maxy) - fmaxf(b1miny, b2miny), 0.f);
            float inter = iw * ih;
            float a2 = M.gw * M.gh;
            float iou = inter / fmaxf(pa + a2 - inter, 1e-6f);
            float cdx = px - M.gx, cdy = py - M.gy;
            float center_d = cdx * cdx + cdy * cdy;
            float ew = fmaxf(fmaxf(b1maxx, b2maxx) - fminf(b1minx, b2minx), 0.f);
            float eh = fmaxf(fmaxf(b1maxy, b2maxy) - fminf(b1miny, b2miny), 0.f);
            float encl = ew * ew + eh * eh;
            float ciou = iou - center_d / fmaxf(encl, 1e-6f);
            const float FOUR_OVER_PI2 = 4.f / (float)(M_PI * M_PI);
            float dat = atanf(pw / fmaxf(ph, 1e-6f)) - atanf(M.gw / fmaxf(M.gh, 1e-6f));
            float v = FOUR_OVER_PI2 * dat * dat;
            float alpha = v / fmaxf(1.f - iou + v, 1e-6f);
            ciou = ciou - alpha * v;

            // ---- conf correction (identical formulas to k_main for exact cancel) ----
            float noobj0 = hitmask ? 0.f : 1.f;
            float add = splus(-tc);            // bce(conf, 1), mask 1
            float sub = splus(tc) * noobj0;    // what k_main already added

            atomicAdd(&s_conf, (double)(add - sub));
            atomicAdd(&s_mask, (double)(1.f - noobj0));
            atomicAdd(&s_loc,  (double)(1.f - ciou));
            atomicAdd(&s_cls,  (double)clssum);
        }
    }

    __syncthreads();
    if (threadIdx.x == 0) {
        atomicAdd(&g_conf_num, s_conf);
        atomicAdd(&g_mask_sum, s_mask);
        atomicAdd(&g_loc_sum,  s_loc);
        atomicAdd(&g_cls_sum,  s_cls);
        __threadfence();
        int d = atomicAdd(&g_done, 1);
        if (d == CORR_BLOCKS - 1) {
            double nobj = (g_mcount > 0) ? (double)g_mcount : 1.0;
            double loss = g_loc_sum / nobj * BOX_RATIO
                        + g_cls_sum / (nobj * (double)NC) * CLS_RATIO
                        + g_conf_num / fmax(g_mask_sum, 1.0) * BALANCE_L * OBJ_RATIO;
            out[0] = (float)loss;
        }
    }
}

// ---------------- launcher ----------------
extern "C" void kernel_launch(void* const* d_in, const int* in_sizes, int n_in,
                              void* d_out, int out_size) {
    const float* input   = (const float*)d_in[0];
    const float* targets = (const float*)d_in[1];
    float* out = (float*)d_out;
    (void)in_sizes; (void)n_in; (void)out_size;

    k_match<<<1, 32>>>(targets);
    dim3 grid(NXB, BS);
    k_main<<<grid, 256>>>(input, targets);
    k_corr<<<CORR_BLOCKS, 256>>>(input, targets, out);
}

// round 4
// speedup vs baseline: 3.4355x; 1.8186x over previous
#include <cuda_runtime.h>
#include <math.h>
#include <stdint.h>

// ---------------- problem constants (l = 2, 76x76 head) ----------------
#define IN_H   76
#define IN_W   76
#define PLANE  (IN_H * IN_W)        // 5776
#define BS     32
#define NT     20                   // targets per image
#define NA     3
#define NC     80
#define CELLS  (NA * PLANE)         // 17328 per batch item

__device__ __constant__ float c_aw9[9] = {1.5f, 2.375f, 5.f, 4.5f, 9.5f, 9.f, 17.75f, 24.f, 57.375f};
__device__ __constant__ float c_ah9[9] = {2.f, 4.5f, 3.5f, 9.375f, 6.875f, 18.25f, 13.75f, 30.375f, 50.125f};
__device__ __constant__ float c_awl[3] = {1.5f, 2.375f, 5.f};
__device__ __constant__ float c_ahl[3] = {2.f, 4.5f, 3.5f};

#define BOX_RATIO 0.05
#define CLS_RATIO 1.0
#define BALANCE_L 4.0
#define OBJ_RATIO (5.0 * 608.0 * 608.0 / (416.0 * 416.0))

// ---------------- device scratch ----------------
struct Matched { int b, a, gi, gj, cls; float gx, gy, gw, gh; };

__device__ double g_conf_num;
__device__ double g_mask_sum;
__device__ double g_loc_sum;
__device__ double g_cls_sum;
__device__ int    g_mcount;
__device__ int    g_done;
__device__ Matched g_matched[BS * NT];

__device__ __forceinline__ float sigfast(float x) { return __fdividef(1.f, 1.f + __expf(-x)); }
// softplus(x) = -log(1 - sigmoid(x)) = bce(sigmoid(x), 0); bce(sigmoid(x),1) = softplus(-x)
__device__ __forceinline__ float splus(float x) { return __logf(1.f + __expf(x)); }

// ---------------- kernel 1: zero accumulators + parallel target matching ----------------
// One thread per (b, t) target: 640 threads, 1 block.
__global__ void __launch_bounds__(BS * NT) k_match(const float* __restrict__ targets) {
    const int tid = threadIdx.x;          // 0..639
    const int b = tid / NT;
    const int t = tid - b * NT;

    if (tid == 0) {
        g_conf_num = 0.0; g_mask_sum = 0.0; g_loc_sum = 0.0; g_cls_sum = 0.0;
        g_mcount = 0; g_done = 0;
    }

    __shared__ int s_flat[BS * NT];

    const float* tp = targets + tid * 5;
    float x = tp[0] * (float)IN_W;
    float y = tp[1] * (float)IN_H;
    float w = tp[2] * (float)IN_W;
    float h = tp[3] * (float)IN_H;

    // zero-centered wh IoU against all 9 anchors, argmax (first max wins)
    float best = -1.f; int bn = 0;
    #pragma unroll
    for (int a = 0; a < 9; a++) {
        float inter = fminf(w, c_aw9[a]) * fminf(h, c_ah9[a]);
        float uni   = w * h + c_aw9[a] * c_ah9[a] - inter;
        float r = inter / uni;
        if (r > best) { best = r; bn = a; }
    }

    int flat = -1;
    int gi = 0, gj = 0;
    if (bn < NA) {   // ANCHORS_MASK[2] = [0,1,2]
        gi = min(max((int)floorf(x), 0), IN_W - 1);
        gj = min(max((int)floorf(y), 0), IN_H - 1);
        flat = (bn * IN_H + gj) * IN_W + gi;
    }
    s_flat[tid] = flat;
    __syncthreads();

    // last-wins dedupe: final iff no later valid target in same batch hits same cell
    if (flat >= 0) {
        bool fin = true;
        for (int t2 = t + 1; t2 < NT; t2++)
            if (s_flat[b * NT + t2] == flat) { fin = false; break; }
        if (fin) {
            int idx = atomicAdd(&g_mcount, 1);
            Matched m;
            m.b = b; m.a = bn; m.gi = gi; m.gj = gj;
            m.gx = x; m.gy = y; m.gw = w; m.gh = h;
            m.cls = (int)tp[4];
            g_matched[idx] = m;
        }
    }
}

// ---------------- kernel 2: dense conf pass (obj=0 everywhere) ----------------
#define CPB 512                        // cells per block (256 thr x 2)
#define NXB ((CELLS + CPB - 1) / CPB)  // 34 x-blocks
__global__ void __launch_bounds__(256) k_main(const float* __restrict__ input,
                                              const float* __restrict__ targets) {
    const int b = blockIdx.y;

    __shared__ float sminx[NT], smaxx[NT], sminy[NT], smaxy[NT], sarea[NT];
    if (threadIdx.x < NT) {
        const float* tp = targets + (b * NT + threadIdx.x) * 5;
        float gx = tp[0] * (float)IN_W, gy = tp[1] * (float)IN_H;
        float gw = tp[2] * (float)IN_W, gh = tp[3] * (float)IN_H;
        sminx[threadIdx.x] = gx - gw * 0.5f; smaxx[threadIdx.x] = gx + gw * 0.5f;
        sminy[threadIdx.x] = gy - gh * 0.5f; smaxy[threadIdx.x] = gy + gh * 0.5f;
        sarea[threadIdx.x] = gw * gh;
    }
    __syncthreads();

    float cnum = 0.f, cmask = 0.f;
    const float* binp = input + (size_t)b * 255 * PLANE;

    #pragma unroll
    for (int chunk = 0; chunk < CPB / 256; chunk++) {
        int m = blockIdx.x * CPB + chunk * 256 + threadIdx.x;
        if (m >= CELLS) break;
        int a   = m / PLANE;
        int rem = m - a * PLANE;
        int i   = rem / IN_W;
        int j   = rem - i * IN_W;

        const float* base = binp + (size_t)a * 85 * PLANE + rem;
        float tx = base[0];
        float ty = base[PLANE];
        float tw = base[2 * PLANE];
        float th = base[3 * PLANE];
        float tc = base[4 * PLANE];

        float px = (float)j + sigfast(tx);
        float py = (float)i + sigfast(ty);
        float pw = __expf(tw) * c_awl[a];
        float ph = __expf(th) * c_ahl[a];

        float pminx = px - pw * 0.5f, pmaxx = px + pw * 0.5f;
        float pminy = py - ph * 0.5f, pmaxy = py + ph * 0.5f;
        float pa = pw * ph;

        // iou > 0.5  <=>  3*inter > sarea + pa   (no division)
        bool hit = false;
        #pragma unroll
        for (int t = 0; t < NT; t++) {
            float iw = fmaxf(fminf(smaxx[t], pmaxx) - fmaxf(sminx[t], pminx), 0.f);
            float ih = fmaxf(fminf(smaxy[t], pmaxy) - fmaxf(sminy[t], pminy), 0.f);
            float inter = iw * ih;
            hit = hit || (3.f * inter > sarea[t] + pa);
        }
        float noobj = hit ? 0.f : 1.f;
        cnum  += splus(tc) * noobj;   // bce(sigmoid(tc), 0) * noobj
        cmask += noobj;
    }

    #pragma unroll
    for (int o = 16; o > 0; o >>= 1) {
        cnum  += __shfl_down_sync(0xffffffffu, cnum,  o);
        cmask += __shfl_down_sync(0xffffffffu, cmask, o);
    }
    __shared__ float rn[8], rm[8];
    int wid = threadIdx.x >> 5, lane = threadIdx.x & 31;
    if (lane == 0) { rn[wid] = cnum; rm[wid] = cmask; }
    __syncthreads();
    if (wid == 0) {
        float n = (lane < 8) ? rn[lane] : 0.f;
        float k = (lane < 8) ? rm[lane] : 0.f;
        #pragma unroll
        for (int o = 4; o > 0; o >>= 1) {
            n += __shfl_down_sync(0xffffffffu, n, o);
            k += __shfl_down_sync(0xffffffffu, k, o);
        }
        if (lane == 0) {
            atomicAdd(&g_conf_num, (double)n);
            atomicAdd(&g_mask_sum, (double)k);
        }
    }
}

// ---------------- kernel 3: matched-cell loc/cls + conf correction + final ----------------
#define CORR_BLOCKS 80
__global__ void __launch_bounds__(256) k_corr(const float* __restrict__ input,
                                              const float* __restrict__ targets,
                                              float* __restrict__ out) {
    const int lane = threadIdx.x & 31;
    const int widx = (blockIdx.x * blockDim.x + threadIdx.x) >> 5;

    __shared__ double s_conf, s_mask, s_loc, s_cls;
    if (threadIdx.x == 0) { s_conf = 0.0; s_mask = 0.0; s_loc = 0.0; s_cls = 0.0; }
    __syncthreads();

    if (widx < g_mcount) {
        Matched M = g_matched[widx];
        const float* base = input + ((size_t)M.b * 255 + (size_t)M.a * 85) * PLANE
                                  + (size_t)M.gj * IN_W + M.gi;

        float v5 = (lane < 5) ? base[(size_t)lane * PLANE] : 0.f;
        float tx = __shfl_sync(0xffffffffu, v5, 0);
        float ty = __shfl_sync(0xffffffffu, v5, 1);
        float tw = __shfl_sync(0xffffffffu, v5, 2);
        float th = __shfl_sync(0xffffffffu, v5, 3);
        float tc = __shfl_sync(0xffffffffu, v5, 4);

        // class BCE split across lanes: one-hot target
        float clssum = 0.f;
        #pragma unroll
        for (int c = lane; c < NC; c += 32) {
            float tv = base[(size_t)(5 + c) * PLANE];
            clssum += (c == M.cls) ? splus(-tv) : splus(tv);
        }

        float px = (float)M.gi + sigfast(tx);
        float py = (float)M.gj + sigfast(ty);
        float pw = __expf(tw) * c_awl[M.a];
        float ph = __expf(th) * c_ahl[M.a];
        float b1minx = px - pw * 0.5f, b1maxx = px + pw * 0.5f;
        float b1miny = py - ph * 0.5f, b1maxy = py + ph * 0.5f;
        float pa = pw * ph;

        // ignore-IoU vs 20 gt boxes (predicate form, same as k_main)
        bool hit_t = false;
        if (lane < NT) {
            const float* tp = targets + (M.b * NT + lane) * 5;
            float gx = tp[0] * (float)IN_W, gy = tp[1] * (float)IN_H;
            float gw = tp[2] * (float)IN_W, gh = tp[3] * (float)IN_H;
            float gminx = gx - gw * 0.5f, gmaxx = gx + gw * 0.5f;
            float gminy = gy - gh * 0.5f, gmaxy = gy + gh * 0.5f;
            float iw2 = fmaxf(fminf(gmaxx, b1maxx) - fmaxf(gminx, b1minx), 0.f);
            float ih2 = fmaxf(fminf(gmaxy, b1maxy) - fmaxf(gminy, b1miny), 0.f);
            float in2 = iw2 * ih2;
            hit_t = (3.f * in2 > gw * gh + pa);
        }
        unsigned hitmask = __ballot_sync(0xffffffffu, hit_t);
        #pragma unroll
        for (int o = 16; o > 0; o >>= 1)
            clssum += __shfl_down_sync(0xffffffffu, clssum, o);

        if (lane == 0) {
            // ---- CIoU (exact reference math) ----
            float b2minx = M.gx - M.gw * 0.5f, b2maxx = M.gx + M.gw * 0.5f;
            float b2miny = M.gy - M.gh * 0.5f, b2maxy = M.gy + M.gh * 0.5f;
            float iw = fmaxf(fminf(b1maxx, b2maxx) - fmaxf(b1minx, b2minx), 0.f);
            float ih = fmaxf(fminf(b1maxy, b2maxy) - fmaxf(b1miny, b2miny), 0.f);
            float inter = iw * ih;
            float a2 = M.gw * M.gh;
            float iou = inter / fmaxf(pa + a2 - inter, 1e-6f);
            float cdx = px - M.gx, cdy = py - M.gy;
            float center_d = cdx * cdx + cdy * cdy;
            float ew = fmaxf(fmaxf(b1maxx, b2maxx) - fminf(b1minx, b2minx), 0.f);
            float eh = fmaxf(fmaxf(b1maxy, b2maxy) - fminf(b1miny, b2miny), 0.f);
            float encl = ew * ew + eh * eh;
            float ciou = iou - center_d / fmaxf(encl, 1e-6f);
            const float FOUR_OVER_PI2 = 4.f / (float)(M_PI * M_PI);
            float dat = atanf(pw / fmaxf(ph, 1e-6f)) - atanf(M.gw / fmaxf(M.gh, 1e-6f));
            float v = FOUR_OVER_PI2 * dat * dat;
            float alpha = v / fmaxf(1.f - iou + v, 1e-6f);
            ciou = ciou - alpha * v;

            // ---- conf correction (identical formulas to k_main for exact cancel) ----
            float noobj0 = hitmask ? 0.f : 1.f;
            float add = splus(-tc);            // bce(conf, 1), mask 1
            float sub = splus(tc) * noobj0;    // what k_main already added

            atomicAdd(&s_conf, (double)(add - sub));
            atomicAdd(&s_mask, (double)(1.f - noobj0));
            atomicAdd(&s_loc,  (double)(1.f - ciou));
            atomicAdd(&s_cls,  (double)clssum);
        }
    }

    __syncthreads();
    if (threadIdx.x == 0) {
        atomicAdd(&g_conf_num, s_conf);
        atomicAdd(&g_mask_sum, s_mask);
        atomicAdd(&g_loc_sum,  s_loc);
        atomicAdd(&g_cls_sum,  s_cls);
        __threadfence();
        int d = atomicAdd(&g_done, 1);
        if (d == CORR_BLOCKS - 1) {
            double nobj = (g_mcount > 0) ? (double)g_mcount : 1.0;
            double loss = g_loc_sum / nobj * BOX_RATIO
                        + g_cls_sum / (nobj * (double)NC) * CLS_RATIO
                        + g_conf_num / fmax(g_mask_sum, 1.0) * BALANCE_L * OBJ_RATIO;
            out[0] = (float)loss;
        }
    }
}

// ---------------- launcher ----------------
extern "C" void kernel_launch(void* const* d_in, const int* in_sizes, int n_in,
                              void* d_out, int out_size) {
    const float* input   = (const float*)d_in[0];
    const float* targets = (const float*)d_in[1];
    float* out = (float*)d_out;
    (void)in_sizes; (void)n_in; (void)out_size;

    k_match<<<1, BS * NT>>>(targets);
    dim3 grid(NXB, BS);
    k_main<<<grid, 256>>>(input, targets);
    k_corr<<<CORR_BLOCKS, 256>>>(input, targets, out);
}

// round 5
// speedup vs baseline: 4.1966x; 1.2215x over previous
#include <cuda_runtime.h>
#include <math.h>
#include <stdint.h>

// ---------------- problem constants (l = 2, 76x76 head) ----------------
#define IN_H   76
#define IN_W   76
#define PLANE  (IN_H * IN_W)        // 5776 (divisible by 4)
#define BS     32
#define NT     20
#define NA     3
#define NC     80
#define CELLS  (NA * PLANE)         // 17328 per batch item
#define VCELLS (CELLS / 4)          // 4332 float4 groups per batch item
#define NVB    ((VCELLS + 255) / 256)  // 17 dense x-blocks

__device__ __constant__ float c_aw9[9] = {1.5f, 2.375f, 5.f, 4.5f, 9.5f, 9.f, 17.75f, 24.f, 57.375f};
__device__ __constant__ float c_ah9[9] = {2.f, 4.5f, 3.5f, 9.375f, 6.875f, 18.25f, 13.75f, 30.375f, 50.125f};
__device__ __constant__ float c_awl[3] = {1.5f, 2.375f, 5.f};
__device__ __constant__ float c_ahl[3] = {2.f, 4.5f, 3.5f};

#define BOX_RATIO 0.05
#define CLS_RATIO 1.0
#define BALANCE_L 4.0
#define OBJ_RATIO (5.0 * 608.0 * 608.0 / (416.0 * 416.0))

// ---------------- device scratch (zero-initialized at load; self-reset per call) ----------------
struct Matched { int b, a, gi, gj, cls; float gx, gy, gw, gh; };

__device__ double g_conf_num = 0.0;
__device__ double g_mask_sum = 0.0;
__device__ double g_loc_sum  = 0.0;
__device__ double g_cls_sum  = 0.0;
__device__ int    g_mcount   = 0;
__device__ int    g_done     = 0;
__device__ Matched g_matched[BS * NT];

__device__ __forceinline__ float sigfast(float x) { return __fdividef(1.f, 1.f + __expf(-x)); }
// softplus(x) = bce(sigmoid(x), 0);  bce(sigmoid(x), 1) = softplus(-x)
__device__ __forceinline__ float splus(float x) { return __logf(1.f + __expf(x)); }

// ---------------- kernel 1: fused dense conf pass + target matching ----------------
// grid (NVB+1, BS): x < NVB -> dense pass, x == NVB -> match the 20 targets of batch y
__global__ void __launch_bounds__(256) k_fused(const float* __restrict__ input,
                                               const float* __restrict__ targets) {
    const int b = blockIdx.y;

    if (blockIdx.x == NVB) {
        // -------- match block: one thread per target --------
        __shared__ int s_flat[NT];
        const int t = threadIdx.x;
        int flat = -1, bn = 0, gi = 0, gj = 0;
        float x = 0.f, y = 0.f, w = 0.f, h = 0.f;
        if (t < NT) {
            const float* tp = targets + (b * NT + t) * 5;
            x = tp[0] * (float)IN_W;
            y = tp[1] * (float)IN_H;
            w = tp[2] * (float)IN_W;
            h = tp[3] * (float)IN_H;
            float best = -1.f;
            #pragma unroll
            for (int a = 0; a < 9; a++) {
                float inter = fminf(w, c_aw9[a]) * fminf(h, c_ah9[a]);
                float uni   = w * h + c_aw9[a] * c_ah9[a] - inter;
                float r = inter / uni;
                if (r > best) { best = r; bn = a; }
            }
            if (bn < NA) {
                gi = min(max((int)floorf(x), 0), IN_W - 1);
                gj = min(max((int)floorf(y), 0), IN_H - 1);
                flat = (bn * IN_H + gj) * IN_W + gi;
            }
            s_flat[t] = flat;
        }
        __syncthreads();
        if (t < NT && flat >= 0) {
            bool fin = true;
            for (int t2 = t + 1; t2 < NT; t2++)
                if (s_flat[t2] == flat) { fin = false; break; }
            if (fin) {
                int idx = atomicAdd(&g_mcount, 1);
                Matched m;
                m.b = b; m.a = bn; m.gi = gi; m.gj = gj;
                m.gx = x; m.gy = y; m.gw = w; m.gh = h;
                m.cls = (int)targets[(b * NT + t) * 5 + 4];
                g_matched[idx] = m;
            }
        }
        return;
    }

    // -------- dense block: 4 consecutive cells per thread (float4) --------
    __shared__ float sminx[NT], smaxx[NT], sminy[NT], smaxy[NT], sarea[NT];
    if (threadIdx.x < NT) {
        const float* tp = targets + (b * NT + threadIdx.x) * 5;
        float gx = tp[0] * (float)IN_W, gy = tp[1] * (float)IN_H;
        float gw = tp[2] * (float)IN_W, gh = tp[3] * (float)IN_H;
        sminx[threadIdx.x] = gx - gw * 0.5f; smaxx[threadIdx.x] = gx + gw * 0.5f;
        sminy[threadIdx.x] = gy - gh * 0.5f; smaxy[threadIdx.x] = gy + gh * 0.5f;
        sarea[threadIdx.x] = gw * gh;
    }
    __syncthreads();

    float cnum = 0.f, cmask = 0.f;
    const int v = blockIdx.x * 256 + threadIdx.x;   // float4 group id within batch
    if (v < VCELLS) {
        const int m0  = v * 4;                       // first cell (same anchor, same row for all 4)
        const int a   = m0 / PLANE;
        const int rem = m0 - a * PLANE;
        const int i   = rem / IN_W;
        const int j   = rem - i * IN_W;

        const float* base = input + ((size_t)b * 255 + (size_t)a * 85) * PLANE + rem;
        float4 tx = *(const float4*)(base);
        float4 ty = *(const float4*)(base + PLANE);
        float4 tw = *(const float4*)(base + 2 * PLANE);
        float4 th = *(const float4*)(base + 3 * PLANE);
        float4 tc = *(const float4*)(base + 4 * PLANE);

        float pminx[4], pmaxx[4], pminy[4], pmaxy[4], pa[4], tcv[4];
        {
            const float txa[4] = {tx.x, tx.y, tx.z, tx.w};
            const float tya[4] = {ty.x, ty.y, ty.z, ty.w};
            const float twa[4] = {tw.x, tw.y, tw.z, tw.w};
            const float tha[4] = {th.x, th.y, th.z, th.w};
            const float tca[4] = {tc.x, tc.y, tc.z, tc.w};
            #pragma unroll
            for (int k = 0; k < 4; k++) {
                float px = (float)(j + k) + sigfast(txa[k]);
                float py = (float)i       + sigfast(tya[k]);
                float pw = __expf(twa[k]) * c_awl[a];
                float ph = __expf(tha[k]) * c_ahl[a];
                pminx[k] = px - pw * 0.5f; pmaxx[k] = px + pw * 0.5f;
                pminy[k] = py - ph * 0.5f; pmaxy[k] = py + ph * 0.5f;
                pa[k] = pw * ph;
                tcv[k] = tca[k];
            }
        }

        bool hit[4] = {false, false, false, false};
        #pragma unroll
        for (int t = 0; t < NT; t++) {
            const float tminx = sminx[t], tmaxx = smaxx[t];
            const float tminy = sminy[t], tmaxy = smaxy[t];
            const float tar = sarea[t];
            #pragma unroll
            for (int k = 0; k < 4; k++) {
                float iw = fmaxf(fminf(tmaxx, pmaxx[k]) - fmaxf(tminx, pminx[k]), 0.f);
                float ih = fmaxf(fminf(tmaxy, pmaxy[k]) - fmaxf(tminy, pminy[k]), 0.f);
                float inter = iw * ih;
                hit[k] = hit[k] || (3.f * inter > tar + pa[k]);   // iou > 0.5, division-free
            }
        }
        #pragma unroll
        for (int k = 0; k < 4; k++) {
            float noobj = hit[k] ? 0.f : 1.f;
            cnum  += splus(tcv[k]) * noobj;
            cmask += noobj;
        }
    }

    #pragma unroll
    for (int o = 16; o > 0; o >>= 1) {
        cnum  += __shfl_down_sync(0xffffffffu, cnum,  o);
        cmask += __shfl_down_sync(0xffffffffu, cmask, o);
    }
    __shared__ float rn[8], rm[8];
    int wid = threadIdx.x >> 5, lane = threadIdx.x & 31;
    if (lane == 0) { rn[wid] = cnum; rm[wid] = cmask; }
    __syncthreads();
    if (wid == 0) {
        float n = (lane < 8) ? rn[lane] : 0.f;
        float k = (lane < 8) ? rm[lane] : 0.f;
        #pragma unroll
        for (int o = 4; o > 0; o >>= 1) {
            n += __shfl_down_sync(0xffffffffu, n, o);
            k += __shfl_down_sync(0xffffffffu, k, o);
        }
        if (lane == 0) {
            atomicAdd(&g_conf_num, (double)n);
            atomicAdd(&g_mask_sum, (double)k);
        }
    }
}

// ---------------- kernel 2: matched-cell loc/cls + conf correction + final + self-reset ----------------
#define CORR_BLOCKS 80
__global__ void __launch_bounds__(256) k_corr(const float* __restrict__ input,
                                              const float* __restrict__ targets,
                                              float* __restrict__ out) {
    const int lane = threadIdx.x & 31;
    const int widx = (blockIdx.x * blockDim.x + threadIdx.x) >> 5;

    __shared__ double s_conf, s_mask, s_loc, s_cls;
    if (threadIdx.x == 0) { s_conf = 0.0; s_mask = 0.0; s_loc = 0.0; s_cls = 0.0; }
    __syncthreads();

    if (widx < g_mcount) {
        Matched M = g_matched[widx];
        const float* base = input + ((size_t)M.b * 255 + (size_t)M.a * 85) * PLANE
                                  + (size_t)M.gj * IN_W + M.gi;

        float v5 = (lane < 5) ? base[(size_t)lane * PLANE] : 0.f;
        float tx = __shfl_sync(0xffffffffu, v5, 0);
        float ty = __shfl_sync(0xffffffffu, v5, 1);
        float tw = __shfl_sync(0xffffffffu, v5, 2);
        float th = __shfl_sync(0xffffffffu, v5, 3);
        float tc = __shfl_sync(0xffffffffu, v5, 4);

        float clssum = 0.f;
        #pragma unroll
        for (int c = lane; c < NC; c += 32) {
            float tv = base[(size_t)(5 + c) * PLANE];
            clssum += (c == M.cls) ? splus(-tv) : splus(tv);
        }

        float px = (float)M.gi + sigfast(tx);
        float py = (float)M.gj + sigfast(ty);
        float pw = __expf(tw) * c_awl[M.a];
        float ph = __expf(th) * c_ahl[M.a];
        float b1minx = px - pw * 0.5f, b1maxx = px + pw * 0.5f;
        float b1miny = py - ph * 0.5f, b1maxy = py + ph * 0.5f;
        float pa = pw * ph;

        bool hit_t = false;
        if (lane < NT) {
            const float* tp = targets + (M.b * NT + lane) * 5;
            float gx = tp[0] * (float)IN_W, gy = tp[1] * (float)IN_H;
            float gw = tp[2] * (float)IN_W, gh = tp[3] * (float)IN_H;
            float gminx = gx - gw * 0.5f, gmaxx = gx + gw * 0.5f;
            float gminy = gy - gh * 0.5f, gmaxy = gy + gh * 0.5f;
            float iw2 = fmaxf(fminf(gmaxx, b1maxx) - fmaxf(gminx, b1minx), 0.f);
            float ih2 = fmaxf(fminf(gmaxy, b1maxy) - fmaxf(gminy, b1miny), 0.f);
            float in2 = iw2 * ih2;
            hit_t = (3.f * in2 > gw * gh + pa);
        }
        unsigned hitmask = __ballot_sync(0xffffffffu, hit_t);
        #pragma unroll
        for (int o = 16; o > 0; o >>= 1)
            clssum += __shfl_down_sync(0xffffffffu, clssum, o);

        if (lane == 0) {
            float b2minx = M.gx - M.gw * 0.5f, b2maxx = M.gx + M.gw * 0.5f;
            float b2miny = M.gy - M.gh * 0.5f, b2maxy = M.gy + M.gh * 0.5f;
            float iw = fmaxf(fminf(b1maxx, b2maxx) - fmaxf(b1minx, b2minx), 0.f);
            float ih = fmaxf(fminf(b1maxy, b2maxy) - fmaxf(b1miny, b2miny), 0.f);
            float inter = iw * ih;
            float a2 = M.gw * M.gh;
            float iou = inter / fmaxf(pa + a2 - inter, 1e-6f);
            float cdx = px - M.gx, cdy = py - M.gy;
            float center_d = cdx * cdx + cdy * cdy;
            float ew = fmaxf(fmaxf(b1maxx, b2maxx) - fminf(b1minx, b2minx), 0.f);
            float eh = fmaxf(fmaxf(b1maxy, b2maxy) - fminf(b1miny, b2miny), 0.f);
            float encl = ew * ew + eh * eh;
            float ciou = iou - center_d / fmaxf(encl, 1e-6f);
            const float FOUR_OVER_PI2 = 4.f / (float)(M_PI * M_PI);
            float dat = atanf(pw / fmaxf(ph, 1e-6f)) - atanf(M.gw / fmaxf(M.gh, 1e-6f));
            float v = FOUR_OVER_PI2 * dat * dat;
            float alpha = v / fmaxf(1.f - iou + v, 1e-6f);
            ciou = ciou - alpha * v;

            float noobj0 = hitmask ? 0.f : 1.f;
            float add = splus(-tc);
            float sub = splus(tc) * noobj0;

            atomicAdd(&s_conf, (double)(add - sub));
            atomicAdd(&s_mask, (double)(1.f - noobj0));
            atomicAdd(&s_loc,  (double)(1.f - ciou));
            atomicAdd(&s_cls,  (double)clssum);
        }
    }

    __syncthreads();
    if (threadIdx.x == 0) {
        atomicAdd(&g_conf_num, s_conf);
        atomicAdd(&g_mask_sum, s_mask);
        atomicAdd(&g_loc_sum,  s_loc);
        atomicAdd(&g_cls_sum,  s_cls);
        __threadfence();
        int d = atomicAdd(&g_done, 1);
        if (d == CORR_BLOCKS - 1) {
            double nobj = (g_mcount > 0) ? (double)g_mcount : 1.0;
            double loss = g_loc_sum / nobj * BOX_RATIO
                        + g_cls_sum / (nobj * (double)NC) * CLS_RATIO
                        + g_conf_num / fmax(g_mask_sum, 1.0) * BALANCE_L * OBJ_RATIO;
            out[0] = (float)loss;
            // self-reset for next graph replay (all other blocks already arrived)
            g_conf_num = 0.0; g_mask_sum = 0.0; g_loc_sum = 0.0; g_cls_sum = 0.0;
            g_mcount = 0; g_done = 0;
        }
    }
}

// ---------------- launcher ----------------
extern "C" void kernel_launch(void* const* d_in, const int* in_sizes, int n_in,
                              void* d_out, int out_size) {
    const float* input   = (const float*)d_in[0];
    const float* targets = (const float*)d_in[1];
    float* out = (float*)d_out;
    (void)in_sizes; (void)n_in; (void)out_size;

    dim3 grid(NVB + 1, BS);
    k_fused<<<grid, 256>>>(input, targets);
    k_corr<<<CORR_BLOCKS, 256>>>(input, targets, out);
}

// round 6
// speedup vs baseline: 5.0000x; 1.1914x over previous
#include <cuda_runtime.h>
#include <math.h>
#include <stdint.h>

// ---------------- problem constants (l = 2, 76x76 head) ----------------
#define IN_H   76
#define IN_W   76
#define PLANE  (IN_H * IN_W)        // 5776 (divisible by 4)
#define BS     32
#define NT     20
#define NA     3
#define NC     80
#define CELLS  (NA * PLANE)         // 17328 per batch item
#define VCELLS (CELLS / 4)          // 4332 float4 groups per batch item
#define NVB    ((VCELLS + 255) / 256)  // 17 dense x-blocks
#define TOTAL_BLOCKS ((NVB + 1) * BS)  // 576

__device__ __constant__ float c_aw9[9] = {1.5f, 2.375f, 5.f, 4.5f, 9.5f, 9.f, 17.75f, 24.f, 57.375f};
__device__ __constant__ float c_ah9[9] = {2.f, 4.5f, 3.5f, 9.375f, 6.875f, 18.25f, 13.75f, 30.375f, 50.125f};
__device__ __constant__ float c_awl[3] = {1.5f, 2.375f, 5.f};
__device__ __constant__ float c_ahl[3] = {2.f, 4.5f, 3.5f};

#define BOX_RATIO 0.05
#define CLS_RATIO 1.0
#define BALANCE_L 4.0
#define OBJ_RATIO (5.0 * 608.0 * 608.0 / (416.0 * 416.0))

// ---------------- device scratch (zero-initialized at load; self-reset per call) ----------------
__device__ double g_conf_num = 0.0;
__device__ double g_mask_sum = 0.0;
__device__ double g_loc_sum  = 0.0;
__device__ double g_cls_sum  = 0.0;
__device__ int    g_nobj     = 0;
__device__ int    g_done     = 0;

__device__ __forceinline__ float sigfast(float x) { return __fdividef(1.f, 1.f + __expf(-x)); }
// softplus(x) = bce(sigmoid(x), 0);  bce(sigmoid(x), 1) = softplus(-x)
__device__ __forceinline__ float splus(float x) { return __logf(1.f + __expf(x)); }

struct SMatch { int a, gi, gj, cls; float gx, gy, gw, gh; };

// ---------------- single fused kernel ----------------
// grid (NVB+1, BS):
//   blockIdx.x < NVB  -> dense conf pass (float4, obj=0 assumption)
//   blockIdx.x == NVB -> per-batch match + matched-cell loc/cls/conf-correction
// last finished block assembles the loss and self-resets the accumulators.
__global__ void __launch_bounds__(256) k_fused(const float* __restrict__ input,
                                               const float* __restrict__ targets,
                                               float* __restrict__ out) {
    const int b = blockIdx.y;
    const int tid = threadIdx.x;
    const int wid = tid >> 5, lane = tid & 31;

    // target boxes in feature scale (both block kinds need them)
    __shared__ float sminx[NT], smaxx[NT], sminy[NT], smaxy[NT], sarea[NT];

    if (blockIdx.x == NVB) {
        // ======== match + correction block for batch item b ========
        __shared__ int s_flat[NT];
        __shared__ int s_cnt;
        __shared__ SMatch s_m[NT];
        __shared__ double s_conf, s_mask, s_loc, s_cls;
        if (tid == 0) { s_cnt = 0; s_conf = 0.0; s_mask = 0.0; s_loc = 0.0; s_cls = 0.0; }
        __syncthreads();

        int flat = -1, bn = 0, gi = 0, gj = 0;
        float x = 0.f, y = 0.f, w = 0.f, h = 0.f;
        if (tid < NT) {
            const float* tp = targets + (b * NT + tid) * 5;
            x = tp[0] * (float)IN_W;
            y = tp[1] * (float)IN_H;
            w = tp[2] * (float)IN_W;
            h = tp[3] * (float)IN_H;
            sminx[tid] = x - w * 0.5f; smaxx[tid] = x + w * 0.5f;
            sminy[tid] = y - h * 0.5f; smaxy[tid] = y + h * 0.5f;
            sarea[tid] = w * h;
            float best = -1.f;
            #pragma unroll
            for (int a = 0; a < 9; a++) {
                float inter = fminf(w, c_aw9[a]) * fminf(h, c_ah9[a]);
                float uni   = w * h + c_aw9[a] * c_ah9[a] - inter;
                float r = inter / uni;
                if (r > best) { best = r; bn = a; }
            }
            if (bn < NA) {   // ANCHORS_MASK[2] = [0,1,2]
                gi = min(max((int)floorf(x), 0), IN_W - 1);
                gj = min(max((int)floorf(y), 0), IN_H - 1);
                flat = (bn * IN_H + gj) * IN_W + gi;
            }
            s_flat[tid] = flat;
        }
        __syncthreads();
        if (tid < NT && flat >= 0) {
            // last-wins dedupe: final iff no later valid target hits the same cell
            bool fin = true;
            for (int t2 = tid + 1; t2 < NT; t2++)
                if (s_flat[t2] == flat) { fin = false; break; }
            if (fin) {
                int idx = atomicAdd(&s_cnt, 1);
                SMatch m; m.a = bn; m.gi = gi; m.gj = gj;
                m.gx = x; m.gy = y; m.gw = w; m.gh = h;
                m.cls = (int)targets[(b * NT + tid) * 5 + 4];
                s_m[idx] = m;
            }
        }
        __syncthreads();

        const int cnt = s_cnt;
        for (int c = wid; c < cnt; c += 8) {
            SMatch M = s_m[c];
            const float* base = input + ((size_t)b * 255 + (size_t)M.a * 85) * PLANE
                                      + (size_t)M.gj * IN_W + M.gi;

            float v5 = (lane < 5) ? base[(size_t)lane * PLANE] : 0.f;
            float tx = __shfl_sync(0xffffffffu, v5, 0);
            float ty = __shfl_sync(0xffffffffu, v5, 1);
            float tw = __shfl_sync(0xffffffffu, v5, 2);
            float th = __shfl_sync(0xffffffffu, v5, 3);
            float tc = __shfl_sync(0xffffffffu, v5, 4);

            // class BCE split across lanes, one-hot target
            float clssum = 0.f;
            #pragma unroll
            for (int cc = lane; cc < NC; cc += 32) {
                float tv = base[(size_t)(5 + cc) * PLANE];
                clssum += (cc == M.cls) ? splus(-tv) : splus(tv);
            }

            float px = (float)M.gi + sigfast(tx);
            float py = (float)M.gj + sigfast(ty);
            float pw = __expf(tw) * c_awl[M.a];
            float ph = __expf(th) * c_ahl[M.a];
            float b1minx = px - pw * 0.5f, b1maxx = px + pw * 0.5f;
            float b1miny = py - ph * 0.5f, b1maxy = py + ph * 0.5f;
            float pa = pw * ph;

            // ignore-IoU vs the 20 gt boxes (predicate form identical to dense pass)
            bool hit_t = false;
            if (lane < NT) {
                float iw2 = fmaxf(fminf(smaxx[lane], b1maxx) - fmaxf(sminx[lane], b1minx), 0.f);
                float ih2 = fmaxf(fminf(smaxy[lane], b1maxy) - fmaxf(sminy[lane], b1miny), 0.f);
                float in2 = iw2 * ih2;
                hit_t = (3.f * in2 > sarea[lane] + pa);
            }
            unsigned hitmask = __ballot_sync(0xffffffffu, hit_t);
            #pragma unroll
            for (int o = 16; o > 0; o >>= 1)
                clssum += __shfl_down_sync(0xffffffffu, clssum, o);

            if (lane == 0) {
                // ---- CIoU (exact reference math) ----
                float b2minx = M.gx - M.gw * 0.5f, b2maxx = M.gx + M.gw * 0.5f;
                float b2miny = M.gy - M.gh * 0.5f, b2maxy = M.gy + M.gh * 0.5f;
                float iw = fmaxf(fminf(b1maxx, b2maxx) - fmaxf(b1minx, b2minx), 0.f);
                float ih = fmaxf(fminf(b1maxy, b2maxy) - fmaxf(b1miny, b2miny), 0.f);
                float inter = iw * ih;
                float a2 = M.gw * M.gh;
                float iou = inter / fmaxf(pa + a2 - inter, 1e-6f);
                float cdx = px - M.gx, cdy = py - M.gy;
                float center_d = cdx * cdx + cdy * cdy;
                float ew = fmaxf(fmaxf(b1maxx, b2maxx) - fminf(b1minx, b2minx), 0.f);
                float eh = fmaxf(fmaxf(b1maxy, b2maxy) - fminf(b1miny, b2miny), 0.f);
                float encl = ew * ew + eh * eh;
                float ciou = iou - center_d / fmaxf(encl, 1e-6f);
                const float FOUR_OVER_PI2 = 4.f / (float)(M_PI * M_PI);
                float dat = atanf(pw / fmaxf(ph, 1e-6f)) - atanf(M.gw / fmaxf(M.gh, 1e-6f));
                float v = FOUR_OVER_PI2 * dat * dat;
                float alpha = v / fmaxf(1.f - iou + v, 1e-6f);
                ciou = ciou - alpha * v;

                // ---- conf correction (identical formulas to dense pass for exact cancel) ----
                float noobj0 = hitmask ? 0.f : 1.f;
                float add = splus(-tc);            // bce(conf, 1), mask 1
                float sub = splus(tc) * noobj0;    // what the dense pass already added

                atomicAdd(&s_conf, (double)(add - sub));
                atomicAdd(&s_mask, (double)(1.f - noobj0));
                atomicAdd(&s_loc,  (double)(1.f - ciou));
                atomicAdd(&s_cls,  (double)clssum);
            }
        }
        __syncthreads();
        if (tid == 0) {
            atomicAdd(&g_conf_num, s_conf);
            atomicAdd(&g_mask_sum, s_mask);
            atomicAdd(&g_loc_sum,  s_loc);
            atomicAdd(&g_cls_sum,  s_cls);
            atomicAdd(&g_nobj, cnt);
        }
    } else {
        // ======== dense conf block: 4 consecutive cells per thread ========
        if (tid < NT) {
            const float* tp = targets + (b * NT + tid) * 5;
            float gx = tp[0] * (float)IN_W, gy = tp[1] * (float)IN_H;
            float gw = tp[2] * (float)IN_W, gh = tp[3] * (float)IN_H;
            sminx[tid] = gx - gw * 0.5f; smaxx[tid] = gx + gw * 0.5f;
            sminy[tid] = gy - gh * 0.5f; smaxy[tid] = gy + gh * 0.5f;
            sarea[tid] = gw * gh;
        }
        __syncthreads();

        float cnum = 0.f, cmask = 0.f;
        const int v = blockIdx.x * 256 + tid;
        if (v < VCELLS) {
            const int m0  = v * 4;
            const int a   = m0 / PLANE;
            const int rem = m0 - a * PLANE;
            const int i   = rem / IN_W;
            const int j   = rem - i * IN_W;

            const float* base = input + ((size_t)b * 255 + (size_t)a * 85) * PLANE + rem;
            float4 tx = *(const float4*)(base);
            float4 ty = *(const float4*)(base + PLANE);
            float4 tw = *(const float4*)(base + 2 * PLANE);
            float4 th = *(const float4*)(base + 3 * PLANE);
            float4 tc = *(const float4*)(base + 4 * PLANE);

            float pminx[4], pmaxx[4], pminy[4], pmaxy[4], pa[4], tcv[4];
            {
                const float txa[4] = {tx.x, tx.y, tx.z, tx.w};
                const float tya[4] = {ty.x, ty.y, ty.z, ty.w};
                const float twa[4] = {tw.x, tw.y, tw.z, tw.w};
                const float tha[4] = {th.x, th.y, th.z, th.w};
                const float tca[4] = {tc.x, tc.y, tc.z, tc.w};
                #pragma unroll
                for (int k = 0; k < 4; k++) {
                    float px = (float)(j + k) + sigfast(txa[k]);
                    float py = (float)i       + sigfast(tya[k]);
                    float pw = __expf(twa[k]) * c_awl[a];
                    float ph = __expf(tha[k]) * c_ahl[a];
                    pminx[k] = px - pw * 0.5f; pmaxx[k] = px + pw * 0.5f;
                    pminy[k] = py - ph * 0.5f; pmaxy[k] = py + ph * 0.5f;
                    pa[k] = pw * ph;
                    tcv[k] = tca[k];
                }
            }

            bool hit[4] = {false, false, false, false};
            #pragma unroll
            for (int t = 0; t < NT; t++) {
                const float tminx = sminx[t], tmaxx = smaxx[t];
                const float tminy = sminy[t], tmaxy = smaxy[t];
                const float tar = sarea[t];
                #pragma unroll
                for (int k = 0; k < 4; k++) {
                    float iw = fmaxf(fminf(tmaxx, pmaxx[k]) - fmaxf(tminx, pminx[k]), 0.f);
                    float ih = fmaxf(fminf(tmaxy, pmaxy[k]) - fmaxf(tminy, pminy[k]), 0.f);
                    float inter = iw * ih;
                    hit[k] = hit[k] || (3.f * inter > tar + pa[k]);   // iou > 0.5, no division
                }
            }
            #pragma unroll
            for (int k = 0; k < 4; k++) {
                float noobj = hit[k] ? 0.f : 1.f;
                cnum  += splus(tcv[k]) * noobj;
                cmask += noobj;
            }
        }

        #pragma unroll
        for (int o = 16; o > 0; o >>= 1) {
            cnum  += __shfl_down_sync(0xffffffffu, cnum,  o);
            cmask += __shfl_down_sync(0xffffffffu, cmask, o);
        }
        __shared__ float rn[8], rm[8];
        if (lane == 0) { rn[wid] = cnum; rm[wid] = cmask; }
        __syncthreads();
        if (wid == 0) {
            float n = (lane < 8) ? rn[lane] : 0.f;
            float k = (lane < 8) ? rm[lane] : 0.f;
            #pragma unroll
            for (int o = 4; o > 0; o >>= 1) {
                n += __shfl_down_sync(0xffffffffu, n, o);
                k += __shfl_down_sync(0xffffffffu, k, o);
            }
            if (lane == 0) {
                atomicAdd(&g_conf_num, (double)n);
                atomicAdd(&g_mask_sum, (double)k);
            }
        }
        __syncthreads();
    }

    // ======== grid-wide completion: last block assembles the loss ========
    if (tid == 0) {
        __threadfence();
        int d = atomicAdd(&g_done, 1);
        if (d == TOTAL_BLOCKS - 1) {
            double nobj = (g_nobj > 0) ? (double)g_nobj : 1.0;
            double loss = g_loc_sum / nobj * BOX_RATIO
                        + g_cls_sum / (nobj * (double)NC) * CLS_RATIO
                        + g_conf_num / fmax(g_mask_sum, 1.0) * BALANCE_L * OBJ_RATIO;
            out[0] = (float)loss;
            // self-reset for the next graph replay
            g_conf_num = 0.0; g_mask_sum = 0.0; g_loc_sum = 0.0; g_cls_sum = 0.0;
            g_nobj = 0; g_done = 0;
        }
    }
}

// ---------------- launcher ----------------
extern "C" void kernel_launch(void* const* d_in, const int* in_sizes, int n_in,
                              void* d_out, int out_size) {
    const float* input   = (const float*)d_in[0];
    const float* targets = (const float*)d_in[1];
    float* out = (float*)d_out;
    (void)in_sizes; (void)n_in; (void)out_size;

    dim3 grid(NVB + 1, BS);
    k_fused<<<grid, 256>>>(input, targets, out);
}

// round 8
// speedup vs baseline: 5.6992x; 1.1398x over previous
#include <cuda_runtime.h>
#include <math.h>
#include <stdint.h>

// ---------------- problem constants (l = 2, 76x76 head) ----------------
#define IN_H   76
#define IN_W   76
#define PLANE  (IN_H * IN_W)        // 5776 (divisible by 4)
#define BS     32
#define NT     20
#define NA     3
#define NC     80
#define CELLS  (NA * PLANE)         // 17328 per batch item
#define VCELLS (CELLS / 4)          // 4332 float4 groups per batch item
#define NVB    ((VCELLS + 255) / 256)  // 17 dense x-blocks
#define TOTAL_BLOCKS ((NVB + 1) * BS)  // 576

__device__ __constant__ float c_aw9[9] = {1.5f, 2.375f, 5.f, 4.5f, 9.5f, 9.f, 17.75f, 24.f, 57.375f};
__device__ __constant__ float c_ah9[9] = {2.f, 4.5f, 3.5f, 9.375f, 6.875f, 18.25f, 13.75f, 30.375f, 50.125f};
__device__ __constant__ float c_awl[3] = {1.5f, 2.375f, 5.f};
__device__ __constant__ float c_ahl[3] = {2.f, 4.5f, 3.5f};

#define BOX_RATIO 0.05
#define CLS_RATIO 1.0
#define BALANCE_L 4.0
#define OBJ_RATIO (5.0 * 608.0 * 608.0 / (416.0 * 416.0))

// ---------------- device scratch (zero-initialized at load; self-reset per call) ----------------
__device__ double g_conf_num = 0.0;
__device__ double g_mask_sum = 0.0;
__device__ double g_loc_sum  = 0.0;
__device__ double g_cls_sum  = 0.0;
__device__ int    g_nobj     = 0;
__device__ int    g_done     = 0;

__device__ __forceinline__ float sigfast(float x) { return __fdividef(1.f, 1.f + __expf(-x)); }
// softplus(x) = bce(sigmoid(x), 0);  bce(sigmoid(x), 1) = softplus(-x)
__device__ __forceinline__ float splus(float x) { return __logf(1.f + __expf(x)); }

struct SMatch { int a, gi, gj, cls; float gx, gy, gw, gh; };

// ---------------- single fused kernel ----------------
// grid (NVB+1, BS): x < NVB -> dense conf pass, x == NVB -> match + correction.
// launch_bounds(256,4): regs<=64 -> 4 blocks/SM -> 592 slots >= 576 blocks = one wave.
__global__ void __launch_bounds__(256, 4) k_fused(const float* __restrict__ input,
                                                  const float* __restrict__ targets,
                                                  float* __restrict__ out) {
    const int b = blockIdx.y;
    const int tid = threadIdx.x;
    const int wid = tid >> 5, lane = tid & 31;

    if (blockIdx.x == NVB) {
        // ======== match + correction block for batch item b ========
        __shared__ float sminx[NT], smaxx[NT], sminy[NT], smaxy[NT], sarea[NT];
        __shared__ int s_flat[NT];
        __shared__ int s_cnt;
        __shared__ SMatch s_m[NT];
        __shared__ double s_conf, s_mask, s_loc, s_cls;
        if (tid == 0) { s_cnt = 0; s_conf = 0.0; s_mask = 0.0; s_loc = 0.0; s_cls = 0.0; }
        __syncthreads();

        int flat = -1, bn = 0, gi = 0, gj = 0;
        float x = 0.f, y = 0.f, w = 0.f, h = 0.f;
        if (tid < NT) {
            const float* tp = targets + (b * NT + tid) * 5;
            x = tp[0] * (float)IN_W;
            y = tp[1] * (float)IN_H;
            w = tp[2] * (float)IN_W;
            h = tp[3] * (float)IN_H;
            sminx[tid] = x - w * 0.5f; smaxx[tid] = x + w * 0.5f;
            sminy[tid] = y - h * 0.5f; smaxy[tid] = y + h * 0.5f;
            sarea[tid] = w * h;
            float best = -1.f;
            #pragma unroll
            for (int a = 0; a < 9; a++) {
                float inter = fminf(w, c_aw9[a]) * fminf(h, c_ah9[a]);
                float uni   = w * h + c_aw9[a] * c_ah9[a] - inter;
                float r = inter / uni;
                if (r > best) { best = r; bn = a; }
            }
            if (bn < NA) {   // ANCHORS_MASK[2] = [0,1,2]
                gi = min(max((int)floorf(x), 0), IN_W - 1);
                gj = min(max((int)floorf(y), 0), IN_H - 1);
                flat = (bn * IN_H + gj) * IN_W + gi;
            }
            s_flat[tid] = flat;
        }
        __syncthreads();
        if (tid < NT && flat >= 0) {
            // last-wins dedupe
            bool fin = true;
            for (int t2 = tid + 1; t2 < NT; t2++)
                if (s_flat[t2] == flat) { fin = false; break; }
            if (fin) {
                int idx = atomicAdd(&s_cnt, 1);
                SMatch m; m.a = bn; m.gi = gi; m.gj = gj;
                m.gx = x; m.gy = y; m.gw = w; m.gh = h;
                m.cls = (int)targets[(b * NT + tid) * 5 + 4];
                s_m[idx] = m;
            }
        }
        __syncthreads();

        const int cnt = s_cnt;
        for (int c = wid; c < cnt; c += 8) {
            SMatch M = s_m[c];
            const float* base = input + ((size_t)b * 255 + (size_t)M.a * 85) * PLANE
                                      + (size_t)M.gj * IN_W + M.gi;

            float v5 = (lane < 5) ? base[(size_t)lane * PLANE] : 0.f;
            float tx = __shfl_sync(0xffffffffu, v5, 0);
            float ty = __shfl_sync(0xffffffffu, v5, 1);
            float tw = __shfl_sync(0xffffffffu, v5, 2);
            float th = __shfl_sync(0xffffffffu, v5, 3);
            float tc = __shfl_sync(0xffffffffu, v5, 4);

            float clssum = 0.f;
            #pragma unroll
            for (int cc = lane; cc < NC; cc += 32) {
                float tv = base[(size_t)(5 + cc) * PLANE];
                clssum += (cc == M.cls) ? splus(-tv) : splus(tv);
            }

            float px = (float)M.gi + sigfast(tx);
            float py = (float)M.gj + sigfast(ty);
            float pw = __expf(tw) * c_awl[M.a];
            float ph = __expf(th) * c_ahl[M.a];
            float b1minx = px - pw * 0.5f, b1maxx = px + pw * 0.5f;
            float b1miny = py - ph * 0.5f, b1maxy = py + ph * 0.5f;
            float pa = pw * ph;

            // ignore-IoU vs 20 gt boxes — same scalar sequence as dense path
            bool hit_t = false;
            if (lane < NT) {
                float ia = fminf(smaxx[lane], b1maxx);
                float ib = fmaxf(sminx[lane], b1minx);
                float iw2 = fmaxf(ia - ib, 0.f);
                float ca = fminf(smaxy[lane], b1maxy);
                float cb = fmaxf(sminy[lane], b1miny);
                float ih2 = ca - cb;
                float diff = fmaf(iw2 * ih2, 3.f, -sarea[lane]);
                hit_t = diff > pa;
            }
            unsigned hitmask = __ballot_sync(0xffffffffu, hit_t);
            #pragma unroll
            for (int o = 16; o > 0; o >>= 1)
                clssum += __shfl_down_sync(0xffffffffu, clssum, o);

            if (lane == 0) {
                // ---- CIoU (exact reference math) ----
                float b2minx = M.gx - M.gw * 0.5f, b2maxx = M.gx + M.gw * 0.5f;
                float b2miny = M.gy - M.gh * 0.5f, b2maxy = M.gy + M.gh * 0.5f;
                float iw = fmaxf(fminf(b1maxx, b2maxx) - fmaxf(b1minx, b2minx), 0.f);
                float ih = fmaxf(fminf(b1maxy, b2maxy) - fmaxf(b1miny, b2miny), 0.f);
                float inter = iw * ih;
                float a2 = M.gw * M.gh;
                float iou = inter / fmaxf(pa + a2 - inter, 1e-6f);
                float cdx = px - M.gx, cdy = py - M.gy;
                float center_d = cdx * cdx + cdy * cdy;
                float ew = fmaxf(fmaxf(b1maxx, b2maxx) - fminf(b1minx, b2minx), 0.f);
                float eh = fmaxf(fmaxf(b1maxy, b2maxy) - fminf(b1miny, b2miny), 0.f);
                float encl = ew * ew + eh * eh;
                float ciou = iou - center_d / fmaxf(encl, 1e-6f);
                const float FOUR_OVER_PI2 = 4.f / (float)(M_PI * M_PI);
                float dat = atanf(pw / fmaxf(ph, 1e-6f)) - atanf(M.gw / fmaxf(M.gh, 1e-6f));
                float v = FOUR_OVER_PI2 * dat * dat;
                float alpha = v / fmaxf(1.f - iou + v, 1e-6f);
                ciou = ciou - alpha * v;

                // ---- conf correction (exact cancel vs dense pass) ----
                float noobj0 = hitmask ? 0.f : 1.f;
                float add = splus(-tc);
                float sub = splus(tc) * noobj0;

                atomicAdd(&s_conf, (double)(add - sub));
                atomicAdd(&s_mask, (double)(1.f - noobj0));
                atomicAdd(&s_loc,  (double)(1.f - ciou));
                atomicAdd(&s_cls,  (double)clssum);
            }
        }
        __syncthreads();
        if (tid == 0) {
            atomicAdd(&g_conf_num, s_conf);
            atomicAdd(&g_mask_sum, s_mask);
            atomicAdd(&g_loc_sum,  s_loc);
            atomicAdd(&g_cls_sum,  s_cls);
            atomicAdd(&g_nobj, cnt);
        }
    } else {
        // ======== dense conf block: 4 cells/thread, strength-reduced IoU test ========
        __shared__ float2 s_x[NT];    // {minx, maxx}
        __shared__ float2 s_y[NT];    // {miny, maxy}
        __shared__ float  s_nt[NT];   // -area
        if (tid < NT) {
            const float* tp = targets + (b * NT + tid) * 5;
            float gx = tp[0] * (float)IN_W, gy = tp[1] * (float)IN_H;
            float gw = tp[2] * (float)IN_W, gh = tp[3] * (float)IN_H;
            s_x[tid] = make_float2(gx - gw * 0.5f, gx + gw * 0.5f);
            s_y[tid] = make_float2(gy - gh * 0.5f, gy + gh * 0.5f);
            s_nt[tid] = -(gw * gh);
        }
        __syncthreads();

        float cnum = 0.f, cmask = 0.f;
        const int v = blockIdx.x * 256 + tid;
        if (v < VCELLS) {
            const int m0  = v * 4;
            const int a   = m0 / PLANE;
            const int rem = m0 - a * PLANE;
            const int i   = rem / IN_W;
            const int j   = rem - i * IN_W;

            const float* base = input + ((size_t)b * 255 + (size_t)a * 85) * PLANE + rem;
            float4 tx = *(const float4*)(base);
            float4 ty = *(const float4*)(base + PLANE);
            float4 tw = *(const float4*)(base + 2 * PLANE);
            float4 th = *(const float4*)(base + 3 * PLANE);
            float4 tc = *(const float4*)(base + 4 * PLANE);

            float mnx[4], mxx[4], mny[4], mxy[4], pa[4], maxd[4];
            const float tcv[4] = {tc.x, tc.y, tc.z, tc.w};
            {
                const float txa[4] = {tx.x, tx.y, tx.z, tx.w};
                const float tya[4] = {ty.x, ty.y, ty.z, ty.w};
                const float twa[4] = {tw.x, tw.y, tw.z, tw.w};
                const float tha[4] = {th.x, th.y, th.z, th.w};
                #pragma unroll
                for (int k = 0; k < 4; k++) {
                    float px = (float)(j + k) + sigfast(txa[k]);
                    float py = (float)i       + sigfast(tya[k]);
                    float pw = __expf(twa[k]) * c_awl[a];
                    float ph = __expf(tha[k]) * c_ahl[a];
                    mnx[k] = px - pw * 0.5f; mxx[k] = px + pw * 0.5f;
                    mny[k] = py - ph * 0.5f; mxy[k] = py + ph * 0.5f;
                    pa[k] = pw * ph;
                    maxd[k] = -1e30f;
                }
            }

            // maxd[k] = max_t (3*inter - tar);  hit iff maxd > pa (pa const per cell)
            #pragma unroll
            for (int t = 0; t < NT; t++) {
                const float2 X = s_x[t];
                const float2 Y = s_y[t];
                const float nt = s_nt[t];
                #pragma unroll
                for (int k = 0; k < 4; k++) {
                    float ia = fminf(X.y, mxx[k]);
                    float ib = fmaxf(X.x, mnx[k]);
                    float iw = fmaxf(ia - ib, 0.f);
                    float ca = fminf(Y.y, mxy[k]);
                    float cb = fmaxf(Y.x, mny[k]);
                    float ih = ca - cb;                 // no clamp: if neg, iw>=0 => diff loses max
                    float diff = fmaf(iw * ih, 3.f, nt);
                    maxd[k] = fmaxf(maxd[k], diff);
                }
            }
            #pragma unroll
            for (int k = 0; k < 4; k++) {
                float noobj = (maxd[k] > pa[k]) ? 0.f : 1.f;
                cnum  += splus(tcv[k]) * noobj;
                cmask += noobj;
            }
        }

        #pragma unroll
        for (int o = 16; o > 0; o >>= 1) {
            cnum  += __shfl_down_sync(0xffffffffu, cnum,  o);
            cmask += __shfl_down_sync(0xffffffffu, cmask, o);
        }
        __shared__ float rn[8], rm[8];
        if (lane == 0) { rn[wid] = cnum; rm[wid] = cmask; }
        __syncthreads();
        if (wid == 0) {
            float n = (lane < 8) ? rn[lane] : 0.f;
            float k = (lane < 8) ? rm[lane] : 0.f;
            #pragma unroll
            for (int o = 4; o > 0; o >>= 1) {
                n += __shfl_down_sync(0xffffffffu, n, o);
                k += __shfl_down_sync(0xffffffffu, k, o);
            }
            if (lane == 0) {
                atomicAdd(&g_conf_num, (double)n);
                atomicAdd(&g_mask_sum, (double)k);
            }
        }
        __syncthreads();
    }

    // ======== grid-wide completion: last block assembles the loss ========
    if (tid == 0) {
        __threadfence();
        int d = atomicAdd(&g_done, 1);
        if (d == TOTAL_BLOCKS - 1) {
            double nobj = (g_nobj > 0) ? (double)g_nobj : 1.0;
            double loss = g_loc_sum / nobj * BOX_RATIO
                        + g_cls_sum / (nobj * (double)NC) * CLS_RATIO
                        + g_conf_num / fmax(g_mask_sum, 1.0) * BALANCE_L * OBJ_RATIO;
            out[0] = (float)loss;
            // self-reset for the next graph replay
            g_conf_num = 0.0; g_mask_sum = 0.0; g_loc_sum = 0.0; g_cls_sum = 0.0;
            g_nobj = 0; g_done = 0;
        }
    }
}

// ---------------- launcher ----------------
extern "C" void kernel_launch(void* const* d_in, const int* in_sizes, int n_in,
                              void* d_out, int out_size) {
    const float* input   = (const float*)d_in[0];
    const float* targets = (const float*)d_in[1];
    float* out = (float*)d_out;
    (void)in_sizes; (void)n_in; (void)out_size;

    dim3 grid(NVB + 1, BS);
    k_fused<<<grid, 256>>>(input, targets, out);
}

// round 9
// speedup vs baseline: 5.8099x; 1.0194x over previous
#include <cuda_runtime.h>
#include <math.h>
#include <stdint.h>

// ---------------- problem constants (l = 2, 76x76 head) ----------------
#define IN_H   76
#define IN_W   76
#define PLANE  (IN_H * IN_W)        // 5776 (even)
#define BS     32
#define NT     20
#define NA     3
#define NC     80
#define CELLS  (NA * PLANE)         // 17328 per batch item
#define VCELLS2 (CELLS / 2)         // 8664 float2 groups per batch item
#define NVB    ((VCELLS2 + 255) / 256)  // 34 dense x-blocks
#define TOTAL_BLOCKS ((NVB + 1) * BS)   // 1120

__device__ __constant__ float c_aw9[9] = {1.5f, 2.375f, 5.f, 4.5f, 9.5f, 9.f, 17.75f, 24.f, 57.375f};
__device__ __constant__ float c_ah9[9] = {2.f, 4.5f, 3.5f, 9.375f, 6.875f, 18.25f, 13.75f, 30.375f, 50.125f};
__device__ __constant__ float c_awl[3] = {1.5f, 2.375f, 5.f};
__device__ __constant__ float c_ahl[3] = {2.f, 4.5f, 3.5f};

#define BOX_RATIO 0.05
#define CLS_RATIO 1.0
#define BALANCE_L 4.0
#define OBJ_RATIO (5.0 * 608.0 * 608.0 / (416.0 * 416.0))

// ---------------- device scratch (zero-initialized at load; self-reset per call) ----------------
__device__ double g_conf_num = 0.0;
__device__ double g_mask_sum = 0.0;
__device__ double g_loc_sum  = 0.0;
__device__ double g_cls_sum  = 0.0;
__device__ int    g_nobj     = 0;
__device__ int    g_done     = 0;

__device__ __forceinline__ float sigfast(float x) { return __fdividef(1.f, 1.f + __expf(-x)); }
// softplus(x) = bce(sigmoid(x), 0);  bce(sigmoid(x), 1) = softplus(-x)
__device__ __forceinline__ float splus(float x) { return __logf(1.f + __expf(x)); }

struct SMatch { int a, gi, gj, cls; float gx, gy, gw, gh; };

// ---------------- single fused kernel ----------------
// grid (NVB+1, BS): x < NVB -> dense conf pass (2 cells/thread), x == NVB -> match+correction.
// launch_bounds(256,5): <=48 regs -> 5 blocks/SM -> 40 warps/SM during the main wave.
__global__ void __launch_bounds__(256, 5) k_fused(const float* __restrict__ input,
                                                  const float* __restrict__ targets,
                                                  float* __restrict__ out) {
    const int b = blockIdx.y;
    const int tid = threadIdx.x;
    const int wid = tid >> 5, lane = tid & 31;

    if (blockIdx.x == NVB) {
        // ======== match + correction block for batch item b ========
        __shared__ float sminx[NT], smaxx[NT], sminy[NT], smaxy[NT], sarea[NT];
        __shared__ int s_flat[NT];
        __shared__ int s_cnt;
        __shared__ SMatch s_m[NT];
        __shared__ double s_conf, s_mask, s_loc, s_cls;
        if (tid == 0) { s_cnt = 0; s_conf = 0.0; s_mask = 0.0; s_loc = 0.0; s_cls = 0.0; }
        __syncthreads();

        int flat = -1, bn = 0, gi = 0, gj = 0;
        float x = 0.f, y = 0.f, w = 0.f, h = 0.f;
        if (tid < NT) {
            const float* tp = targets + (b * NT + tid) * 5;
            x = tp[0] * (float)IN_W;
            y = tp[1] * (float)IN_H;
            w = tp[2] * (float)IN_W;
            h = tp[3] * (float)IN_H;
            sminx[tid] = x - w * 0.5f; smaxx[tid] = x + w * 0.5f;
            sminy[tid] = y - h * 0.5f; smaxy[tid] = y + h * 0.5f;
            sarea[tid] = w * h;
            float best = -1.f;
            #pragma unroll
            for (int a = 0; a < 9; a++) {
                float inter = fminf(w, c_aw9[a]) * fminf(h, c_ah9[a]);
                float uni   = w * h + c_aw9[a] * c_ah9[a] - inter;
                float r = inter / uni;
                if (r > best) { best = r; bn = a; }
            }
            if (bn < NA) {   // ANCHORS_MASK[2] = [0,1,2]
                gi = min(max((int)floorf(x), 0), IN_W - 1);
                gj = min(max((int)floorf(y), 0), IN_H - 1);
                flat = (bn * IN_H + gj) * IN_W + gi;
            }
            s_flat[tid] = flat;
        }
        __syncthreads();
        if (tid < NT && flat >= 0) {
            // last-wins dedupe
            bool fin = true;
            for (int t2 = tid + 1; t2 < NT; t2++)
                if (s_flat[t2] == flat) { fin = false; break; }
            if (fin) {
                int idx = atomicAdd(&s_cnt, 1);
                SMatch m; m.a = bn; m.gi = gi; m.gj = gj;
                m.gx = x; m.gy = y; m.gw = w; m.gh = h;
                m.cls = (int)targets[(b * NT + tid) * 5 + 4];
                s_m[idx] = m;
            }
        }
        __syncthreads();

        const int cnt = s_cnt;
        for (int c = wid; c < cnt; c += 8) {
            SMatch M = s_m[c];
            const float* base = input + ((size_t)b * 255 + (size_t)M.a * 85) * PLANE
                                      + (size_t)M.gj * IN_W + M.gi;

            float v5 = (lane < 5) ? base[(size_t)lane * PLANE] : 0.f;
            float tx = __shfl_sync(0xffffffffu, v5, 0);
            float ty = __shfl_sync(0xffffffffu, v5, 1);
            float tw = __shfl_sync(0xffffffffu, v5, 2);
            float th = __shfl_sync(0xffffffffu, v5, 3);
            float tc = __shfl_sync(0xffffffffu, v5, 4);

            float clssum = 0.f;
            #pragma unroll
            for (int cc = lane; cc < NC; cc += 32) {
                float tv = base[(size_t)(5 + cc) * PLANE];
                clssum += (cc == M.cls) ? splus(-tv) : splus(tv);
            }

            float px = (float)M.gi + sigfast(tx);
            float py = (float)M.gj + sigfast(ty);
            float pw = __expf(tw) * c_awl[M.a];
            float ph = __expf(th) * c_ahl[M.a];
            float b1minx = px - pw * 0.5f, b1maxx = px + pw * 0.5f;
            float b1miny = py - ph * 0.5f, b1maxy = py + ph * 0.5f;
            float pa = pw * ph;

            // ignore-IoU vs 20 gt boxes — same scalar sequence as dense path
            bool hit_t = false;
            if (lane < NT) {
                float ia = fminf(smaxx[lane], b1maxx);
                float ib = fmaxf(sminx[lane], b1minx);
                float iw2 = fmaxf(ia - ib, 0.f);
                float ca = fminf(smaxy[lane], b1maxy);
                float cb = fmaxf(sminy[lane], b1miny);
                float ih2 = ca - cb;
                float diff = fmaf(iw2 * ih2, 3.f, -sarea[lane]);
                hit_t = diff > pa;
            }
            unsigned hitmask = __ballot_sync(0xffffffffu, hit_t);
            #pragma unroll
            for (int o = 16; o > 0; o >>= 1)
                clssum += __shfl_down_sync(0xffffffffu, clssum, o);

            if (lane == 0) {
                // ---- CIoU (exact reference math) ----
                float b2minx = M.gx - M.gw * 0.5f, b2maxx = M.gx + M.gw * 0.5f;
                float b2miny = M.gy - M.gh * 0.5f, b2maxy = M.gy + M.gh * 0.5f;
                float iw = fmaxf(fminf(b1maxx, b2maxx) - fmaxf(b1minx, b2minx), 0.f);
                float ih = fmaxf(fminf(b1maxy, b2maxy) - fmaxf(b1miny, b2miny), 0.f);
                float inter = iw * ih;
                float a2 = M.gw * M.gh;
                float iou = inter / fmaxf(pa + a2 - inter, 1e-6f);
                float cdx = px - M.gx, cdy = py - M.gy;
                float center_d = cdx * cdx + cdy * cdy;
                float ew = fmaxf(fmaxf(b1maxx, b2maxx) - fminf(b1minx, b2minx), 0.f);
                float eh = fmaxf(fmaxf(b1maxy, b2maxy) - fminf(b1miny, b2miny), 0.f);
                float encl = ew * ew + eh * eh;
                float ciou = iou - center_d / fmaxf(encl, 1e-6f);
                const float FOUR_OVER_PI2 = 4.f / (float)(M_PI * M_PI);
                float dat = atanf(pw / fmaxf(ph, 1e-6f)) - atanf(M.gw / fmaxf(M.gh, 1e-6f));
                float v = FOUR_OVER_PI2 * dat * dat;
                float alpha = v / fmaxf(1.f - iou + v, 1e-6f);
                ciou = ciou - alpha * v;

                // ---- conf correction (exact cancel vs dense pass) ----
                float noobj0 = hitmask ? 0.f : 1.f;
                float add = splus(-tc);
                float sub = splus(tc) * noobj0;

                atomicAdd(&s_conf, (double)(add - sub));
                atomicAdd(&s_mask, (double)(1.f - noobj0));
                atomicAdd(&s_loc,  (double)(1.f - ciou));
                atomicAdd(&s_cls,  (double)clssum);
            }
        }
        __syncthreads();
        if (tid == 0) {
            atomicAdd(&g_conf_num, s_conf);
            atomicAdd(&g_mask_sum, s_mask);
            atomicAdd(&g_loc_sum,  s_loc);
            atomicAdd(&g_cls_sum,  s_cls);
            atomicAdd(&g_nobj, cnt);
        }
    } else {
        // ======== dense conf block: 2 cells/thread, strength-reduced IoU test ========
        __shared__ float2 s_x[NT];    // {minx, maxx}
        __shared__ float2 s_y[NT];    // {miny, maxy}
        __shared__ float  s_nt[NT];   // -area
        if (tid < NT) {
            const float* tp = targets + (b * NT + tid) * 5;
            float gx = tp[0] * (float)IN_W, gy = tp[1] * (float)IN_H;
            float gw = tp[2] * (float)IN_W, gh = tp[3] * (float)IN_H;
            s_x[tid] = make_float2(gx - gw * 0.5f, gx + gw * 0.5f);
            s_y[tid] = make_float2(gy - gh * 0.5f, gy + gh * 0.5f);
            s_nt[tid] = -(gw * gh);
        }
        __syncthreads();

        float cnum = 0.f, cmask = 0.f;
        const int v = blockIdx.x * 256 + tid;
        if (v < VCELLS2) {
            const int m0  = v * 2;
            const int a   = m0 / PLANE;
            const int rem = m0 - a * PLANE;
            const int i   = rem / IN_W;
            const int j   = rem - i * IN_W;

            const float* base = input + ((size_t)b * 255 + (size_t)a * 85) * PLANE + rem;
            float2 tx = *(const float2*)(base);
            float2 ty = *(const float2*)(base + PLANE);
            float2 tw = *(const float2*)(base + 2 * PLANE);
            float2 th = *(const float2*)(base + 3 * PLANE);
            float2 tc = *(const float2*)(base + 4 * PLANE);

            float mnx[2], mxx[2], mny[2], mxy[2], pa[2], maxd[2];
            const float tcv[2] = {tc.x, tc.y};
            {
                const float txa[2] = {tx.x, tx.y};
                const float tya[2] = {ty.x, ty.y};
                const float twa[2] = {tw.x, tw.y};
                const float tha[2] = {th.x, th.y};
                #pragma unroll
                for (int k = 0; k < 2; k++) {
                    float px = (float)(j + k) + sigfast(txa[k]);
                    float py = (float)i       + sigfast(tya[k]);
                    float pw = __expf(twa[k]) * c_awl[a];
                    float ph = __expf(tha[k]) * c_ahl[a];
                    mnx[k] = px - pw * 0.5f; mxx[k] = px + pw * 0.5f;
                    mny[k] = py - ph * 0.5f; mxy[k] = py + ph * 0.5f;
                    pa[k] = pw * ph;
                    maxd[k] = -1e30f;
                }
            }

            // maxd[k] = max_t (3*inter - tar);  hit iff maxd > pa (pa const per cell)
            #pragma unroll
            for (int t = 0; t < NT; t++) {
                const float2 X = s_x[t];
                const float2 Y = s_y[t];
                const float nt = s_nt[t];
                #pragma unroll
                for (int k = 0; k < 2; k++) {
                    float ia = fminf(X.y, mxx[k]);
                    float ib = fmaxf(X.x, mnx[k]);
                    float iw = fmaxf(ia - ib, 0.f);
                    float ca = fminf(Y.y, mxy[k]);
                    float cb = fmaxf(Y.x, mny[k]);
                    float ih = ca - cb;                 // no clamp: if neg, iw>=0 => diff loses max
                    float diff = fmaf(iw * ih, 3.f, nt);
                    maxd[k] = fmaxf(maxd[k], diff);
                }
            }
            #pragma unroll
            for (int k = 0; k < 2; k++) {
                float noobj = (maxd[k] > pa[k]) ? 0.f : 1.f;
                cnum  += splus(tcv[k]) * noobj;
                cmask += noobj;
            }
        }

        #pragma unroll
        for (int o = 16; o > 0; o >>= 1) {
            cnum  += __shfl_down_sync(0xffffffffu, cnum,  o);
            cmask += __shfl_down_sync(0xffffffffu, cmask, o);
        }
        __shared__ float rn[8], rm[8];
        if (lane == 0) { rn[wid] = cnum; rm[wid] = cmask; }
        __syncthreads();
        if (wid == 0) {
            float n = (lane < 8) ? rn[lane] : 0.f;
            float k = (lane < 8) ? rm[lane] : 0.f;
            #pragma unroll
            for (int o = 4; o > 0; o >>= 1) {
                n += __shfl_down_sync(0xffffffffu, n, o);
                k += __shfl_down_sync(0xffffffffu, k, o);
            }
            if (lane == 0) {
                atomicAdd(&g_conf_num, (double)n);
                atomicAdd(&g_mask_sum, (double)k);
            }
        }
        __syncthreads();
    }

    // ======== grid-wide completion: last block assembles the loss ========
    if (tid == 0) {
        __threadfence();
        int d = atomicAdd(&g_done, 1);
        if (d == TOTAL_BLOCKS - 1) {
            double nobj = (g_nobj > 0) ? (double)g_nobj : 1.0;
            double loss = g_loc_sum / nobj * BOX_RATIO
                        + g_cls_sum / (nobj * (double)NC) * CLS_RATIO
                        + g_conf_num / fmax(g_mask_sum, 1.0) * BALANCE_L * OBJ_RATIO;
            out[0] = (float)loss;
            // self-reset for the next graph replay
            g_conf_num = 0.0; g_mask_sum = 0.0; g_loc_sum = 0.0; g_cls_sum = 0.0;
            g_nobj = 0; g_done = 0;
        }
    }
}

// ---------------- launcher ----------------
extern "C" void kernel_launch(void* const* d_in, const int* in_sizes, int n_in,
                              void* d_out, int out_size) {
    const float* input   = (const float*)d_in[0];
    const float* targets = (const float*)d_in[1];
    float* out = (float*)d_out;
    (void)in_sizes; (void)n_in; (void)out_size;

    dim3 grid(NVB + 1, BS);
    k_fused<<<grid, 256>>>(input, targets, out);
}